// round 10
// baseline (speedup 1.0000x reference)
#include <cuda_runtime.h>

#define BATCH 256
#define NPTS  4096
#define NP2   (NPTS/2)
#define DYN_SMEM (NPTS*16 + NPTS*4)
#define FULLM 0xffffffffu

// ---------- fast double helpers: fp32 seed + 1 Newton step ----------
__device__ __forceinline__ double drecip(double x) {
  double y = (double)__fdividef(1.0f, (float)x);
  y = y * (2.0 - x * y);
  return y;
}
__device__ __forceinline__ double drsqrt(double x) {
  double y = (double)rsqrtf((float)x);
  y = y * (1.5 - 0.5 * x * y * y);
  return y;
}

__device__ __forceinline__ void inv3x3(const float* __restrict__ Km, float* __restrict__ out) {
  double a=Km[0], b=Km[1], c=Km[2], d=Km[3], e=Km[4], f=Km[5], g=Km[6], h=Km[7], i=Km[8];
  double det = a*(e*i - f*h) - b*(d*i - f*g) + c*(d*h - e*g);
  double inv = 1.0 / det;
  out[0]=(float)((e*i - f*h)*inv); out[1]=(float)((c*h - b*i)*inv); out[2]=(float)((b*f - c*e)*inv);
  out[3]=(float)((f*g - d*i)*inv); out[4]=(float)((a*i - c*g)*inv); out[5]=(float)((c*d - a*f)*inv);
  out[6]=(float)((d*h - e*g)*inv); out[7]=(float)((b*g - a*h)*inv); out[8]=(float)((a*e - b*d)*inv);
}

__device__ __forceinline__ int p2i(int a, int b) {
  int mn = a < b ? a : b, mx = a < b ? b : a;
  return mn*(5-mn)/2 + mx;
}

template<int P, int Q>
__device__ __forceinline__ void rot3d(double g[3][3], double Qm[3][3]) {
  constexpr int K2 = 3 - P - Q;
  double apq = g[P][Q];
  double app = g[P][P], aqq = g[Q][Q];
  if (fabs(apq) <= 1e-15 * (fabs(app) + fabs(aqq))) return;
  double tau = (aqq - app) * drecip(2.0 * apq);
  double opt2 = 1.0 + tau*tau;
  double sq = opt2 * drsqrt(opt2);
  double tt = ((tau >= 0.0) ? 1.0 : -1.0) * drecip(fabs(tau) + sq);
  double c = drsqrt(1.0 + tt*tt);
  double s = tt * c;
  double akp = g[K2][P], akq = g[K2][Q];
  double np = c*akp - s*akq, nq = s*akp + c*akq;
  g[K2][P] = np; g[P][K2] = np;
  g[K2][Q] = nq; g[Q][K2] = nq;
  g[P][P] = app - tt*apq;
  g[Q][Q] = aqq + tt*apq;
  g[P][Q] = 0.0; g[Q][P] = 0.0;
  #pragma unroll
  for (int r = 0; r < 3; r++) {
    double qp = Qm[r][P], qq = Qm[r][Q];
    Qm[r][P] = c*qp - s*qq;
    Qm[r][Q] = s*qp + c*qq;
  }
}

// ---------- single fused kernel: one block per batch ----------
__global__ __launch_bounds__(256, 2) void k_fused(const float* __restrict__ kpts0,
                                                  const float* __restrict__ kpts1,
                                                  const float* __restrict__ conf,
                                                  const float* __restrict__ tscale,
                                                  const float* __restrict__ Kmat,
                                                  float* __restrict__ out) {
  const int b = blockIdx.x;
  const int tid = threadIdx.x;
  const int warp = tid >> 5, lane = tid & 31;

  extern __shared__ char dyn[];
  float4* sPa = (float4*)dyn;                  // even points: x00,x01,x10,x11
  float4* sPb = (float4*)(dyn + NP2*16);       // odd points
  float2* sW2 = (float2*)(dyn + NPTS*16);      // weights (pairs)

  __shared__ float sKi[18];
  __shared__ float sred[8][36];
  __shared__ double sd[81];           // D (doubles)
  __shared__ float sT[36];
  __shared__ float sR1[9], sR2[9], st3[3];
  __shared__ double sDinv[9], sUV[18], sSgn;
  __shared__ int sIpiv[9];
  __shared__ int sAffine;

  // ---- phase 0: K inverses ----
  if (tid == 0) {
    float ki0[9], ki1[9];
    inv3x3(Kmat + b*18, ki0);
    inv3x3(Kmat + b*18 + 9, ki1);
    #pragma unroll
    for (int i=0;i<9;i++) { sKi[i]=ki0[i]; sKi[9+i]=ki1[i]; }
    sAffine = (ki0[6]==0.f && ki0[7]==0.f && ki0[8]==1.f &&
               ki1[6]==0.f && ki1[7]==0.f && ki1[8]==1.f) ? 1 : 0;
  }
  __syncthreads();
  float Ki0[9], Ki1[9];
  #pragma unroll
  for (int i=0;i<9;i++){ Ki0[i]=sKi[i]; Ki1[i]=sKi[9+i]; }
  const int affine = sAffine;

  const float4* kp0v = (const float4*)kpts0 + (size_t)b*NP2;
  const float4* kp1v = (const float4*)kpts1 + (size_t)b*NP2;
  const float2* wv2  = (const float2*)conf  + (size_t)b*NP2;

  // ---- phase 1: accumulate T[6][6] (2 points/iter, float4 loads) ----
  {
    float acc[36];
    #pragma unroll
    for (int i=0;i<36;i++) acc[i]=0.f;

    float4 cA = kp0v[tid],      cB = kp1v[tid];      float2 cw = wv2[tid];
    float4 dA = kp0v[tid+256],  dB = kp1v[tid+256];  float2 dw = wv2[tid+256];
    #pragma unroll
    for (int k = 0; k < NP2/256; k++) {
      float4 nA, nB; float2 nw;
      if (k < NP2/256 - 2) {
        nA = kp0v[tid + (k+2)*256];
        nB = kp1v[tid + (k+2)*256];
        nw = wv2[tid + (k+2)*256];
      }
      int n2 = tid + k*256;
      // point A (even)
      {
        float x00 = Ki0[0]*cA.x + Ki0[1]*cA.y + Ki0[2];
        float x01 = Ki0[3]*cA.x + Ki0[4]*cA.y + Ki0[5];
        float x02 = Ki0[6]*cA.x + Ki0[7]*cA.y + Ki0[8];
        float x10 = Ki1[0]*cB.x + Ki1[1]*cB.y + Ki1[2];
        float x11 = Ki1[3]*cB.x + Ki1[4]*cB.y + Ki1[5];
        float x12 = Ki1[6]*cB.x + Ki1[7]*cB.y + Ki1[8];
        sPa[n2] = make_float4(x00, x01, x10, x11);
        float s0a[6] = {x00*x00, x00*x01, x00*x02, x01*x01, x01*x02, x02*x02};
        float s1a[6] = {x10*x10, x10*x11, x10*x12, x11*x11, x11*x12, x12*x12};
        float ws1[6];
        #pragma unroll
        for (int a=0;a<6;a++) ws1[a] = cw.x*s1a[a];
        #pragma unroll
        for (int a=0;a<6;a++)
          #pragma unroll
          for (int bb2=0;bb2<6;bb2++)
            acc[a*6+bb2] = fmaf(ws1[a], s0a[bb2], acc[a*6+bb2]);
      }
      // point B (odd)
      {
        float x00 = Ki0[0]*cA.z + Ki0[1]*cA.w + Ki0[2];
        float x01 = Ki0[3]*cA.z + Ki0[4]*cA.w + Ki0[5];
        float x02 = Ki0[6]*cA.z + Ki0[7]*cA.w + Ki0[8];
        float x10 = Ki1[0]*cB.z + Ki1[1]*cB.w + Ki1[2];
        float x11 = Ki1[3]*cB.z + Ki1[4]*cB.w + Ki1[5];
        float x12 = Ki1[6]*cB.z + Ki1[7]*cB.w + Ki1[8];
        sPb[n2] = make_float4(x00, x01, x10, x11);
        float s0a[6] = {x00*x00, x00*x01, x00*x02, x01*x01, x01*x02, x02*x02};
        float s1a[6] = {x10*x10, x10*x11, x10*x12, x11*x11, x11*x12, x12*x12};
        float ws1[6];
        #pragma unroll
        for (int a=0;a<6;a++) ws1[a] = cw.y*s1a[a];
        #pragma unroll
        for (int a=0;a<6;a++)
          #pragma unroll
          for (int bb2=0;bb2<6;bb2++)
            acc[a*6+bb2] = fmaf(ws1[a], s0a[bb2], acc[a*6+bb2]);
      }
      sW2[n2] = cw;
      cA = dA; cB = dB; cw = dw;
      dA = nA; dB = nB; dw = nw;
    }
    #pragma unroll
    for (int i=0;i<36;i++) {
      acc[i] += __shfl_down_sync(FULLM, acc[i], 16);
      acc[i] += __shfl_down_sync(FULLM, acc[i], 8);
      acc[i] += __shfl_down_sync(FULLM, acc[i], 4);
      acc[i] += __shfl_down_sync(FULLM, acc[i], 2);
      acc[i] += __shfl_down_sync(FULLM, acc[i], 1);
    }
    if (lane == 0) {
      #pragma unroll
      for (int i=0;i<36;i++) sred[warp][i] = acc[i];
    }
    __syncthreads();
    if (tid < 36) {
      float s = 0.f;
      #pragma unroll
      for (int wp=0; wp<8; wp++) s += sred[wp][tid];
      sT[tid] = s;
    }
    __syncthreads();
  }

  // ---- phase 2: eigensolve + essential decomposition (warp 0) ----
  if (warp == 0) {
    // register-resident A: lane j (<9) owns column j
    float colA[9];
    {
      const int lc0 = lane/3, lc1 = lane%3;
      #pragma unroll
      for (int i=0;i<9;i++)
        colA[i] = (lane < 9) ? sT[p2i(i/3, lc0)*6 + p2i(i%3, lc1)] : 0.f;
    }

    // Phase A: register Jacobi (shuffles only), 3 sweeps, sigma-only (no V)
    #pragma unroll
    for (int sweep = 0; sweep < 3; sweep++) {
      #pragma unroll
      for (int r = 0; r < 9; r++) {
        const int bye = (5 * ((2*r) % 9)) % 9;
        float cc[4], ss[4];
        #pragma unroll
        for (int d = 0; d < 4; d++) {
          const int a  = (bye + d + 1) % 9;
          const int b2 = (bye + 8 - d) % 9;
          const int p = a < b2 ? a : b2;
          const int q = a < b2 ? b2 : a;
          float apq = __shfl_sync(FULLM, colA[p], q);
          float app = __shfl_sync(FULLM, colA[p], p);
          float aqq = __shfl_sync(FULLM, colA[q], q);
          float c = 1.f, s = 0.f;
          if (fabsf(apq) > 6e-8f * (fabsf(app) + fabsf(aqq))) {
            float tau = __fdividef(aqq - app, 2.f * apq);
            float t2 = ((tau >= 0.f) ? 1.f : -1.f) / (fabsf(tau) + sqrtf(1.f + tau*tau));
            c = rsqrtf(1.f + t2*t2);
            s = t2 * c;
          }
          cc[d] = c; ss[d] = s;
        }
        // role for this lane
        int t = (lane < 9) ? (lane - bye + 9) % 9 : 0;
        int dp = (t <= 4) ? t : 9 - t;              // pair index 1..4, 0 = bye/inactive
        bool active = (lane < 9) && (t != 0);
        int partner = ((2*bye - lane) % 9 + 9) % 9;
        if (lane >= 9) partner = 0;
        float cmy = cc[0], smy = ss[0];
        if (dp == 2) { cmy = cc[1]; smy = ss[1]; }
        else if (dp == 3) { cmy = cc[2]; smy = ss[2]; }
        else if (dp == 4) { cmy = cc[3]; smy = ss[3]; }
        bool isp = lane < partner;
        // right-mult: column exchange + mix
        #pragma unroll
        for (int i = 0; i < 9; i++) {
          float other = __shfl_sync(FULLM, colA[i], partner);
          if (active)
            colA[i] = isp ? (cmy*colA[i] - smy*other) : (smy*other + cmy*colA[i]);
        }
        // left-mult: row mix within every column
        #pragma unroll
        for (int d = 0; d < 4; d++) {
          const int a  = (bye + d + 1) % 9;
          const int b2 = (bye + 8 - d) % 9;
          const int p = a < b2 ? a : b2;
          const int q = a < b2 ? b2 : a;
          float ap = colA[p], aq = colA[q];
          colA[p] = cc[d]*ap - ss[d]*aq;
          colA[q] = ss[d]*ap + cc[d]*aq;
        }
      }
    }
    // sigma = min diagonal (broadcast to all lanes via shuffles)
    float mv = 3.4e38f;
    #pragma unroll
    for (int j = 0; j < 9; j++) {
      float dj = __shfl_sync(FULLM, colA[j], j);
      mv = fminf(mv, dj);
    }
    double sigma = (double)mv;

    // build D = M - sigma*I in parallel
    double* D = &sd[0];
    if (lane < 9) {
      int i0 = lane/3, j0 = lane%3;
      #pragma unroll
      for (int j=0;j<9;j++) {
        int k0 = j/3, l0 = j%3;
        D[lane*9+j] = (double)sT[p2i(i0,k0)*6 + p2i(j0,l0)];
      }
      D[lane*9+lane] -= sigma;
    }
    __syncwarp();

    // parallel LU with partial pivoting (rows across lanes)
    for (int k=0;k<9;k++) {
      if (lane == 0) {
        int p = k; double mx = fabs(D[k*9+k]);
        for (int i=k+1;i<9;i++){ double v = fabs(D[i*9+k]); if (v > mx){ mx=v; p=i; } }
        sIpiv[k] = p;
      }
      __syncwarp();
      int p = sIpiv[k];
      if (p != k && lane < 9) {
        double t = D[k*9+lane]; D[k*9+lane] = D[p*9+lane]; D[p*9+lane] = t;
      }
      __syncwarp();
      double pv = D[k*9+k];
      if (fabs(pv) < 1e-30) pv = (pv >= 0.0) ? 1e-30 : -1e-30;
      double ipv = drecip(pv);
      if (lane == 0) sDinv[k] = ipv;
      if (lane > k && lane < 9) {
        double l = D[lane*9+k] * ipv;
        D[lane*9+k] = l;
        for (int j=k+1;j<9;j++) D[lane*9+j] -= l * D[k*9+j];
      }
      __syncwarp();
    }

    // lane 0: inverse iteration (3 solves from ones) + 3x3 SVD
    if (lane == 0) {
      double x[9], Dinv[9];
      int ipiv[9];
      #pragma unroll
      for (int k=0;k<9;k++){ x[k]=1.0; Dinv[k]=sDinv[k]; ipiv[k]=sIpiv[k]; }

      for (int it=0; it<3; it++) {
        for (int k=0;k<9;k++){ int p=ipiv[k]; if (p!=k){ double t=x[k]; x[k]=x[p]; x[p]=t; } }
        for (int i=1;i<9;i++){ double s=x[i]; for (int j=0;j<i;j++) s -= D[i*9+j]*x[j]; x[i]=s; }
        for (int i=8;i>=0;i--){ double s=x[i]; for (int j=i+1;j<9;j++) s -= D[i*9+j]*x[j]; x[i]=s*Dinv[i]; }
        double nn = 0.0;
        for (int k=0;k<9;k++) nn += x[k]*x[k];
        double innn = drsqrt(nn);
        for (int k=0;k<9;k++) x[k] *= innn;
      }

      double e[9];
      #pragma unroll
      for (int k=0;k<9;k++) e[k] = x[k];

      double G3[3][3];
      #pragma unroll
      for (int i=0;i<3;i++)
        #pragma unroll
        for (int j=0;j<3;j++)
          G3[i][j] = e[0+i]*e[0+j] + e[3+i]*e[3+j] + e[6+i]*e[6+j];

      double Qm[3][3] = {{1,0,0},{0,1,0},{0,0,1}};
      #pragma unroll
      for (int sw=0; sw<3; sw++) { rot3d<0,1>(G3,Qm); rot3d<0,2>(G3,Qm); rot3d<1,2>(G3,Qm); }

      double lam0=G3[0][0], lam1=G3[1][1], lam2=G3[2][2];
      int o0, o1, o2;
      if (lam0 >= lam1) {
        if (lam0 >= lam2) { o0=0; if (lam1>=lam2){o1=1;o2=2;} else {o1=2;o2=1;} }
        else              { o0=2; o1=0; o2=1; }
      } else {
        if (lam1 >= lam2) { o0=1; if (lam0>=lam2){o1=0;o2=2;} else {o1=2;o2=0;} }
        else              { o0=2; o1=1; o2=0; }
      }
      double v1[3] = {Qm[0][o0], Qm[1][o0], Qm[2][o0]};
      double v2[3] = {Qm[0][o1], Qm[1][o1], Qm[2][o1]};
      double v3[3] = {Qm[0][o2], Qm[1][o2], Qm[2][o2]};

      double u1[3], u2[3], u3[3];
      #pragma unroll
      for (int i=0;i<3;i++) {
        u1[i] = e[3*i+0]*v1[0] + e[3*i+1]*v1[1] + e[3*i+2]*v1[2];
        u2[i] = e[3*i+0]*v2[0] + e[3*i+1]*v2[1] + e[3*i+2]*v2[2];
      }
      double in1 = drsqrt(fmax(u1[0]*u1[0]+u1[1]*u1[1]+u1[2]*u1[2], 1e-300));
      double in2 = drsqrt(fmax(u2[0]*u2[0]+u2[1]*u2[1]+u2[2]*u2[2], 1e-300));
      #pragma unroll
      for (int i=0;i<3;i++){ u1[i]*=in1; u2[i]*=in2; }
      u3[0] = u1[1]*u2[2] - u1[2]*u2[1];
      u3[1] = u1[2]*u2[0] - u1[0]*u2[2];
      u3[2] = u1[0]*u2[1] - u1[1]*u2[0];
      double in3 = drsqrt(fmax(u3[0]*u3[0]+u3[1]*u3[1]+u3[2]*u3[2], 1e-300));
      #pragma unroll
      for (int i=0;i<3;i++) u3[i]*=in3;

      double detU = u1[0]*(u2[1]*u3[2]-u2[2]*u3[1])
                  - u1[1]*(u2[0]*u3[2]-u2[2]*u3[0])
                  + u1[2]*(u2[0]*u3[1]-u2[1]*u3[0]);
      double detV = v1[0]*(v2[1]*v3[2]-v2[2]*v3[1])
                  - v1[1]*(v2[0]*v3[2]-v2[2]*v3[0])
                  + v1[2]*(v2[0]*v3[1]-v2[1]*v3[0]);
      double dd = detU * detV;
      sSgn = (dd > 0.0) ? 1.0 : ((dd < 0.0) ? -1.0 : 0.0);
      #pragma unroll
      for (int i=0;i<3;i++) {
        sUV[i]    = u1[i];
        sUV[3+i]  = u2[i];
        sUV[6+i]  = u3[i];
        sUV[9+i]  = v1[i];
        sUV[12+i] = v2[i];
        sUV[15+i] = v3[i];
        st3[i] = (float)u3[i];
      }
    }
    __syncwarp();

    // parallel R1/R2 build (one element per lane)
    if (lane < 9) {
      int i = lane / 3, j = lane % 3;
      double u1i = sUV[i], u2i = sUV[3+i], u3i = sUV[6+i];
      double v1j = sUV[9+j], v2j = sUV[12+j], v3j = sUV[15+j];
      double sg = sSgn;
      double r1 =  u2i*v1j - u1i*v2j + u3i*v3j;
      double r2 = -u2i*v1j + u1i*v2j + u3i*v3j;
      sR1[lane] = (float)(r1*sg);
      sR2[lane] = (float)(r2*sg);
    }
  }
  __syncthreads();

  // ---- phase 3: cheirality (division-free sign tests) ----
  float R1[9], R2[9];
  #pragma unroll
  for (int i=0;i<9;i++){ R1[i]=sR1[i]; R2[i]=sR2[i]; }
  const float tv0=st3[0], tv1=st3[1], tv2=st3[2];

  float sc0=0.f, sc1=0.f, sc2=0.f, sc3=0.f;
  if (affine) {
    #pragma unroll
    for (int k = 0; k < NP2/256; k++) {
      int n2 = tid + k*256;
      float4 qa = sPa[n2];
      float4 qb = sPb[n2];
      float2 w2 = sW2[n2];
      #pragma unroll
      for (int h = 0; h < 2; h++) {
        float4 q = h ? qb : qa;
        float w = h ? w2.y : w2.x;
        float bb = q.z*q.z + q.w*q.w + 1.0f;
        float bt = q.z*tv0 + q.w*tv1 + tv2;
        {
          float a0 = R1[0]*q.x + R1[1]*q.y + R1[2];
          float a1 = R1[3]*q.x + R1[4]*q.y + R1[5];
          float a2 = R1[6]*q.x + R1[7]*q.y + R1[8];
          float aa = a0*a0 + a1*a1 + a2*a2;
          float ab = a0*q.z + a1*q.w + a2;
          float at = a0*tv0 + a1*tv1 + a2*tv2;
          float det = aa*bb - ab*ab + 1e-9f;
          float n0 = -at*bb + ab*bt;
          float n1 = aa*bt - ab*at;
          bool dpuniversità = det >= 0.f;
          bool dpn = dpuniversità;
          if (dpn ? (n0 > 0.f && n1 > 0.f) : (n0 < 0.f && n1 < 0.f)) sc0 += w;
          if (dpn ? (n0 < 0.f && n1 < 0.f) : (n0 > 0.f && n1 > 0.f)) sc1 += w;
        }
        {
          float a0 = R2[0]*q.x + R2[1]*q.y + R2[2];
          float a1 = R2[3]*q.x + R2[4]*q.y + R2[5];
          float a2 = R2[6]*q.x + R2[7]*q.y + R2[8];
          float aa = a0*a0 + a1*a1 + a2*a2;
          float ab = a0*q.z + a1*q.w + a2;
          float at = a0*tv0 + a1*tv1 + a2*tv2;
          float det = aa*bb - ab*ab + 1e-9f;
          float n0 = -at*bb + ab*bt;
          float n1 = aa*bt - ab*at;
          bool dpn = det >= 0.f;
          if (dpn ? (n0 > 0.f && n1 > 0.f) : (n0 < 0.f && n1 < 0.f)) sc2 += w;
          if (dpn ? (n0 < 0.f && n1 < 0.f) : (n0 > 0.f && n1 > 0.f)) sc3 += w;
        }
      }
    }
  } else {
    const float2* kp0 = (const float2*)(kpts0) + (size_t)b*NPTS;
    const float2* kp1 = (const float2*)(kpts1) + (size_t)b*NPTS;
    const float*  wv  = conf + (size_t)b*NPTS;
    #pragma unroll
    for (int k = 0; k < NPTS/256; k++) {
      int n = tid + k*256;
      float2 p0 = kp0[n]; float2 p1 = kp1[n]; float w = wv[n];
      float x00 = Ki0[0]*p0.x + Ki0[1]*p0.y + Ki0[2];
      float x01 = Ki0[3]*p0.x + Ki0[4]*p0.y + Ki0[5];
      float x02 = Ki0[6]*p0.x + Ki0[7]*p0.y + Ki0[8];
      float x10 = Ki1[0]*p1.x + Ki1[1]*p1.y + Ki1[2];
      float x11 = Ki1[3]*p1.x + Ki1[4]*p1.y + Ki1[5];
      float x12 = Ki1[6]*p1.x + Ki1[7]*p1.y + Ki1[8];
      float bb = x10*x10 + x11*x11 + x12*x12;
      float bt = x10*tv0 + x11*tv1 + x12*tv2;
      {
        float a0 = R1[0]*x00 + R1[1]*x01 + R1[2]*x02;
        float a1 = R1[3]*x00 + R1[4]*x01 + R1[5]*x02;
        float a2 = R1[6]*x00 + R1[7]*x01 + R1[8]*x02;
        float aa = a0*a0 + a1*a1 + a2*a2;
        float ab = a0*x10 + a1*x11 + a2*x12;
        float at = a0*tv0 + a1*tv1 + a2*tv2;
        float det = aa*bb - ab*ab + 1e-9f;
        float n0 = -at*bb + ab*bt;
        float n1 = aa*bt - ab*at;
        bool dpn = det >= 0.f;
        if (dpn ? (n0 > 0.f && n1 > 0.f) : (n0 < 0.f && n1 < 0.f)) sc0 += w;
        if (dpn ? (n0 < 0.f && n1 < 0.f) : (n0 > 0.f && n1 > 0.f)) sc1 += w;
      }
      {
        float a0 = R2[0]*x00 + R2[1]*x01 + R2[2]*x02;
        float a1 = R2[3]*x00 + R2[4]*x01 + R2[5]*x02;
        float a2 = R2[6]*x00 + R2[7]*x01 + R2[8]*x02;
        float aa = a0*a0 + a1*a1 + a2*a2;
        float ab = a0*x10 + a1*x11 + a2*x12;
        float at = a0*tv0 + a1*tv1 + a2*tv2;
        float det = aa*bb - ab*ab + 1e-9f;
        float n0 = -at*bb + ab*bt;
        float n1 = aa*bt - ab*at;
        bool dpn = det >= 0.f;
        if (dpn ? (n0 > 0.f && n1 > 0.f) : (n0 < 0.f && n1 < 0.f)) sc2 += w;
        if (dpn ? (n0 < 0.f && n1 < 0.f) : (n0 > 0.f && n1 > 0.f)) sc3 += w;
      }
    }
  }
  #pragma unroll
  for (int off=16; off; off>>=1) {
    sc0 += __shfl_down_sync(FULLM, sc0, off);
    sc1 += __shfl_down_sync(FULLM, sc1, off);
    sc2 += __shfl_down_sync(FULLM, sc2, off);
    sc3 += __shfl_down_sync(FULLM, sc3, off);
  }
  if (lane == 0) { sred[warp][0]=sc0; sred[warp][1]=sc1; sred[warp][2]=sc2; sred[warp][3]=sc3; }
  __syncthreads();
  if (tid == 0) {
    float s0=0.f, s1=0.f, s2=0.f, s3=0.f;
    #pragma unroll
    for (int wp=0; wp<8; wp++){ s0+=sred[wp][0]; s1+=sred[wp][1]; s2+=sred[wp][2]; s3+=sred[wp][3]; }
    float bs = s0; int bi = 0;
    if (s1 > bs){ bs=s1; bi=1; }
    if (s2 > bs){ bs=s2; bi=2; }
    if (s3 > bs){ bs=s3; bi=3; }
    const float* R = (bi < 2) ? sR1 : sR2;
    float sgn = (bi & 1) ? -1.f : 1.f;
    float ts = tscale[b*2];
    float t0 = (sgn*st3[0])*ts;
    float t1 = (sgn*st3[1])*ts;
    float t2 = (sgn*st3[2])*ts;
    float* o = out + (size_t)b*32;
    o[0]=R[0]; o[1]=R[1]; o[2]=R[2];  o[3]=t0;
    o[4]=R[3]; o[5]=R[4]; o[6]=R[5];  o[7]=t1;
    o[8]=R[6]; o[9]=R[7]; o[10]=R[8]; o[11]=t2;
    o[12]=0.f; o[13]=0.f; o[14]=0.f; o[15]=1.f;
    float ti0 = -(R[0]*t0 + R[3]*t1 + R[6]*t2);
    float ti1 = -(R[1]*t0 + R[4]*t1 + R[7]*t2);
    float ti2 = -(R[2]*t0 + R[5]*t1 + R[8]*t2);
    o[16]=R[0]; o[17]=R[3]; o[18]=R[6]; o[19]=ti0;
    o[20]=R[1]; o[21]=R[4]; o[22]=R[7]; o[23]=ti1;
    o[24]=R[2]; o[25]=R[5]; o[26]=R[8]; o[27]=ti2;
    o[28]=0.f; o[29]=0.f; o[30]=0.f; o[31]=1.f;
  }
}

extern "C" void kernel_launch(void* const* d_in, const int* in_sizes, int n_in,
                              void* d_out, int out_size) {
  const float* kpts0  = (const float*)d_in[0];
  const float* kpts1  = (const float*)d_in[1];
  const float* conf   = (const float*)d_in[2];
  const float* tscale = (const float*)d_in[3];
  const float* Kmat   = (const float*)d_in[4];
  float* out = (float*)d_out;

  cudaFuncSetAttribute(k_fused, cudaFuncAttributeMaxDynamicSharedMemorySize, DYN_SMEM);
  k_fused<<<BATCH, 256, DYN_SMEM>>>(kpts0, kpts1, conf, tscale, Kmat, out);
}

// round 11
// speedup vs baseline: 1.2883x; 1.2883x over previous
#include <cuda_runtime.h>

#define BATCH 256
#define NPTS  4096
#define DYN_SMEM (NPTS*16 + NPTS*4)
#define FULLM 0xffffffffu

// ---------- fast double helpers: fp32 seed + 1 Newton step ----------
__device__ __forceinline__ double drecip(double x) {
  double y = (double)__fdividef(1.0f, (float)x);
  y = y * (2.0 - x * y);
  return y;
}
__device__ __forceinline__ double drsqrt(double x) {
  double y = (double)rsqrtf((float)x);
  y = y * (1.5 - 0.5 * x * y * y);
  return y;
}

__device__ __forceinline__ void inv3x3(const float* __restrict__ Km, float* __restrict__ out) {
  double a=Km[0], b=Km[1], c=Km[2], d=Km[3], e=Km[4], f=Km[5], g=Km[6], h=Km[7], i=Km[8];
  double det = a*(e*i - f*h) - b*(d*i - f*g) + c*(d*h - e*g);
  double inv = 1.0 / det;
  out[0]=(float)((e*i - f*h)*inv); out[1]=(float)((c*h - b*i)*inv); out[2]=(float)((b*f - c*e)*inv);
  out[3]=(float)((f*g - d*i)*inv); out[4]=(float)((a*i - c*g)*inv); out[5]=(float)((c*d - a*f)*inv);
  out[6]=(float)((d*h - e*g)*inv); out[7]=(float)((b*g - a*h)*inv); out[8]=(float)((a*e - b*d)*inv);
}

__device__ __forceinline__ int p2i(int a, int b) {
  int mn = a < b ? a : b, mx = a < b ? b : a;
  return mn*(5-mn)/2 + mx;
}

template<int P, int Q>
__device__ __forceinline__ void rot3d(double g[3][3], double Qm[3][3]) {
  constexpr int K2 = 3 - P - Q;
  double apq = g[P][Q];
  double app = g[P][P], aqq = g[Q][Q];
  if (fabs(apq) <= 1e-15 * (fabs(app) + fabs(aqq))) return;
  double tau = (aqq - app) * drecip(2.0 * apq);
  double opt2 = 1.0 + tau*tau;
  double sq = opt2 * drsqrt(opt2);
  double tt = ((tau >= 0.0) ? 1.0 : -1.0) * drecip(fabs(tau) + sq);
  double c = drsqrt(1.0 + tt*tt);
  double s = tt * c;
  double akp = g[K2][P], akq = g[K2][Q];
  double np = c*akp - s*akq, nq = s*akp + c*akq;
  g[K2][P] = np; g[P][K2] = np;
  g[K2][Q] = nq; g[Q][K2] = nq;
  g[P][P] = app - tt*apq;
  g[Q][Q] = aqq + tt*apq;
  g[P][Q] = 0.0; g[Q][P] = 0.0;
  #pragma unroll
  for (int r = 0; r < 3; r++) {
    double qp = Qm[r][P], qq = Qm[r][Q];
    Qm[r][P] = c*qp - s*qq;
    Qm[r][Q] = s*qp + c*qq;
  }
}

// ---------- single fused kernel: one block per batch ----------
__global__ __launch_bounds__(256, 2) void k_fused(const float* __restrict__ kpts0,
                                                  const float* __restrict__ kpts1,
                                                  const float* __restrict__ conf,
                                                  const float* __restrict__ tscale,
                                                  const float* __restrict__ Kmat,
                                                  float* __restrict__ out) {
  const int b = blockIdx.x;
  const int tid = threadIdx.x;
  const int warp = tid >> 5, lane = tid & 31;

  extern __shared__ char dyn[];
  float4* sP = (float4*)dyn;
  float*  sW = (float*)(dyn + NPTS*16);

  __shared__ float sKi[18];
  __shared__ float sred[8][36];
  __shared__ double sd[81];           // A floats, then D doubles
  __shared__ float sT[36];
  __shared__ float sR1[9], sR2[9], st3[3];
  __shared__ float scs[4], sss[4];
  __shared__ double sDinv[9], sUV[18], sSgn, sSigma, sxd[9];
  __shared__ int sIpiv[9], sPerm[9];
  __shared__ int sAffine;

  // ---- phase 0: K inverses ----
  if (tid == 0) {
    float ki0[9], ki1[9];
    inv3x3(Kmat + b*18, ki0);
    inv3x3(Kmat + b*18 + 9, ki1);
    #pragma unroll
    for (int i=0;i<9;i++) { sKi[i]=ki0[i]; sKi[9+i]=ki1[i]; }
    sAffine = (ki0[6]==0.f && ki0[7]==0.f && ki0[8]==1.f &&
               ki1[6]==0.f && ki1[7]==0.f && ki1[8]==1.f) ? 1 : 0;
  }
  __syncthreads();
  float Ki0[9], Ki1[9];
  #pragma unroll
  for (int i=0;i<9;i++){ Ki0[i]=sKi[i]; Ki1[i]=sKi[9+i]; }
  const int affine = sAffine;

  const float2* kp0 = (const float2*)(kpts0) + (size_t)b*NPTS;
  const float2* kp1 = (const float2*)(kpts1) + (size_t)b*NPTS;
  const float*  wv  = conf + (size_t)b*NPTS;

  // ---- phase 1: accumulate T[6][6] + stage coords (prefetch depth 2) ----
  {
    float acc[36];
    #pragma unroll
    for (int i=0;i<36;i++) acc[i]=0.f;

    float2 c0 = kp0[tid],      c1 = kp1[tid];      float cw = wv[tid];
    float2 d0 = kp0[tid+256],  d1 = kp1[tid+256];  float dw = wv[tid+256];
    #pragma unroll
    for (int k = 0; k < NPTS/256; k++) {
      float2 n0, n1; float nw;
      if (k < NPTS/256 - 2) {
        n0 = kp0[tid + (k+2)*256];
        n1 = kp1[tid + (k+2)*256];
        nw = wv[tid + (k+2)*256];
      }
      float x00 = Ki0[0]*c0.x + Ki0[1]*c0.y + Ki0[2];
      float x01 = Ki0[3]*c0.x + Ki0[4]*c0.y + Ki0[5];
      float x02 = Ki0[6]*c0.x + Ki0[7]*c0.y + Ki0[8];
      float x10 = Ki1[0]*c1.x + Ki1[1]*c1.y + Ki1[2];
      float x11 = Ki1[3]*c1.x + Ki1[4]*c1.y + Ki1[5];
      float x12 = Ki1[6]*c1.x + Ki1[7]*c1.y + Ki1[8];
      int n = tid + k*256;
      sP[n] = make_float4(x00, x01, x10, x11);
      sW[n] = cw;
      float s0a[6] = {x00*x00, x00*x01, x00*x02, x01*x01, x01*x02, x02*x02};
      float s1a[6] = {x10*x10, x10*x11, x10*x12, x11*x11, x11*x12, x12*x12};
      float ws1[6];
      #pragma unroll
      for (int a=0;a<6;a++) ws1[a] = cw*s1a[a];
      #pragma unroll
      for (int a=0;a<6;a++)
        #pragma unroll
        for (int bb2=0;bb2<6;bb2++)
          acc[a*6+bb2] = fmaf(ws1[a], s0a[bb2], acc[a*6+bb2]);
      c0 = d0; c1 = d1; cw = dw;
      d0 = n0; d1 = n1; dw = nw;
    }
    #pragma unroll
    for (int i=0;i<36;i++) {
      acc[i] += __shfl_down_sync(FULLM, acc[i], 16);
      acc[i] += __shfl_down_sync(FULLM, acc[i], 8);
      acc[i] += __shfl_down_sync(FULLM, acc[i], 4);
      acc[i] += __shfl_down_sync(FULLM, acc[i], 2);
      acc[i] += __shfl_down_sync(FULLM, acc[i], 1);
    }
    if (lane == 0) {
      #pragma unroll
      for (int i=0;i<36;i++) sred[warp][i] = acc[i];
    }
    __syncthreads();
    if (tid < 36) {
      float s = 0.f;
      #pragma unroll
      for (int wp=0; wp<8; wp++) s += sred[wp][tid];
      sT[tid] = s;
    }
    __syncthreads();
  }

  // ---- phase 2: eigensolve + essential decomposition (warp 0) ----
  if (warp == 0) {
    float* A = (float*)&sd[0];   // 81 floats (no V needed)

    if (lane < 9) {
      const int i0 = lane / 3, j0 = lane % 3;
      #pragma unroll
      for (int j = 0; j < 9; j++)
        A[lane*9+j] = sT[p2i(i0, j/3)*6 + p2i(j0, j%3)];
    }
    __syncwarp();

    // Phase A: parallel-ordered fp32 Jacobi, 3 sweeps, sigma only (no V)
    for (int sweep = 0; sweep < 3; sweep++) {
      for (int r = 0; r < 9; r++) {
        const int bye = (5 * ((2*r) % 9)) % 9;
        if (lane < 4) {
          int d = lane + 1;
          int a = (bye + d) % 9;
          int bq = (bye + 9 - d) % 9;
          int p = a < bq ? a : bq;
          int q = a < bq ? bq : a;
          float apq = A[p*9+q], app = A[p*9+p], aqq = A[q*9+q];
          float c = 1.0f, s = 0.0f;
          if (fabsf(apq) > 6e-8f * (fabsf(app) + fabsf(aqq))) {
            float tau = __fdividef(aqq - app, 2.0f * apq);
            float t = ((tau >= 0.0f) ? 1.0f : -1.0f) / (fabsf(tau) + sqrtf(1.0f + tau*tau));
            c = rsqrtf(1.0f + t*t);
            s = t * c;
          }
          scs[lane] = c; sss[lane] = s;
        }
        __syncwarp();
        float cr[4], sr[4];
        int pr[4], qr[4];
        #pragma unroll
        for (int d = 0; d < 4; d++) {
          cr[d] = scs[d]; sr[d] = sss[d];
          int a = (bye + d + 1) % 9;
          int bq = (bye + 8 - d) % 9;
          pr[d] = a < bq ? a : bq;
          qr[d] = a < bq ? bq : a;
        }
        if (lane < 9) {
          #pragma unroll
          for (int d = 0; d < 4; d++) {
            int p = pr[d], q = qr[d];
            float vp = A[lane*9+p], vq = A[lane*9+q];
            A[lane*9+p] = cr[d]*vp - sr[d]*vq;
            A[lane*9+q] = sr[d]*vp + cr[d]*vq;
          }
        }
        __syncwarp();
        if (lane < 9) {
          #pragma unroll
          for (int d = 0; d < 4; d++) {
            int p = pr[d], q = qr[d];
            float vp = A[p*9+lane], vq = A[q*9+lane];
            A[p*9+lane] = cr[d]*vp - sr[d]*vq;
            A[q*9+lane] = sr[d]*vp + cr[d]*vq;
          }
        }
        __syncwarp();
      }
    }

    if (lane == 0) {
      float mv = A[0];
      #pragma unroll
      for (int k=1;k<9;k++) mv = fminf(mv, A[k*9+k]);
      sSigma = (double)mv;
    }
    __syncwarp();
    double sigma = sSigma;

    // build D = M - sigma*I in parallel (overwrite A region)
    double* D = &sd[0];
    if (lane < 9) {
      int i0 = lane/3, j0 = lane%3;
      #pragma unroll
      for (int j=0;j<9;j++)
        D[lane*9+j] = (double)sT[p2i(i0, j/3)*6 + p2i(j0, j%3)];
      D[lane*9+lane] -= sigma;
    }
    __syncwarp();

    // parallel LU with partial pivoting (rows across lanes)
    for (int k=0;k<9;k++) {
      if (lane == 0) {
        int p = k; double mx = fabs(D[k*9+k]);
        for (int i=k+1;i<9;i++){ double v = fabs(D[i*9+k]); if (v > mx){ mx=v; p=i; } }
        sIpiv[k] = p;
      }
      __syncwarp();
      int p = sIpiv[k];
      if (p != k && lane < 9) {
        double t = D[k*9+lane]; D[k*9+lane] = D[p*9+lane]; D[p*9+lane] = t;
      }
      __syncwarp();
      double pv = D[k*9+k];
      if (fabs(pv) < 1e-30) pv = (pv >= 0.0) ? 1e-30 : -1e-30;
      double ipv = drecip(pv);
      if (lane == 0) sDinv[k] = ipv;
      if (lane > k && lane < 9) {
        double l = D[lane*9+k] * ipv;
        D[lane*9+k] = l;
        for (int j=k+1;j<9;j++) D[lane*9+j] -= l * D[k*9+j];
      }
      __syncwarp();
    }

    // permutation map: b'[i] = b[perm[i]]
    if (lane == 0) {
      int idx[9];
      #pragma unroll
      for (int i=0;i<9;i++) idx[i]=i;
      for (int k=0;k<9;k++){ int p=sIpiv[k]; int t=idx[k]; idx[k]=idx[p]; idx[p]=t; }
      #pragma unroll
      for (int i=0;i<9;i++) sPerm[i]=idx[i];
    }
    __syncwarp();

    // per-lane row preload
    double row[9]; double dinv_l = 1.0; int permL = 0;
    if (lane < 9) {
      #pragma unroll
      for (int j=0;j<9;j++) row[j] = D[lane*9+j];
      dinv_l = sDinv[lane];
      permL = sPerm[lane];
    }

    // lane-parallel inverse iteration: 3 solves from ones vector
    double rv = 1.0;
    for (int it=0; it<3; it++) {
      if (lane < 9) sxd[lane] = rv;
      __syncwarp();
      if (lane < 9) rv = sxd[permL];
      __syncwarp();
      // forward substitution (unit lower)
      #pragma unroll
      for (int j=0;j<8;j++) {
        double yj = __shfl_sync(FULLM, rv, j);
        if (lane > j && lane < 9) rv -= row[j]*yj;
      }
      // backward substitution
      #pragma unroll
      for (int j=8;j>=0;j--) {
        if (lane == j) rv *= dinv_l;
        double xj = __shfl_sync(FULLM, rv, j);
        if (lane < j) rv -= row[j]*xj;
      }
      // normalize
      double c2 = (lane < 9) ? rv*rv : 0.0;
      #pragma unroll
      for (int off=16; off; off>>=1) c2 += __shfl_xor_sync(FULLM, c2, off);
      rv *= drsqrt(c2);
    }
    if (lane < 9) sxd[lane] = rv;
    __syncwarp();

    // lane 0: 3x3 SVD of E
    if (lane == 0) {
      double e[9];
      #pragma unroll
      for (int k=0;k<9;k++) e[k] = sxd[k];

      double G3[3][3];
      #pragma unroll
      for (int i=0;i<3;i++)
        #pragma unroll
        for (int j=0;j<3;j++)
          G3[i][j] = e[0+i]*e[0+j] + e[3+i]*e[3+j] + e[6+i]*e[6+j];

      double Qm[3][3] = {{1,0,0},{0,1,0},{0,0,1}};
      #pragma unroll
      for (int sw=0; sw<3; sw++) { rot3d<0,1>(G3,Qm); rot3d<0,2>(G3,Qm); rot3d<1,2>(G3,Qm); }

      double lam0=G3[0][0], lam1=G3[1][1], lam2=G3[2][2];
      int o0, o1, o2;
      if (lam0 >= lam1) {
        if (lam0 >= lam2) { o0=0; if (lam1>=lam2){o1=1;o2=2;} else {o1=2;o2=1;} }
        else              { o0=2; o1=0; o2=1; }
      } else {
        if (lam1 >= lam2) { o0=1; if (lam0>=lam2){o1=0;o2=2;} else {o1=2;o2=0;} }
        else              { o0=2; o1=1; o2=0; }
      }
      double v1[3] = {Qm[0][o0], Qm[1][o0], Qm[2][o0]};
      double v2[3] = {Qm[0][o1], Qm[1][o1], Qm[2][o1]};
      double v3[3] = {Qm[0][o2], Qm[1][o2], Qm[2][o2]};

      double u1[3], u2[3], u3[3];
      #pragma unroll
      for (int i=0;i<3;i++) {
        u1[i] = e[3*i+0]*v1[0] + e[3*i+1]*v1[1] + e[3*i+2]*v1[2];
        u2[i] = e[3*i+0]*v2[0] + e[3*i+1]*v2[1] + e[3*i+2]*v2[2];
      }
      double in1 = drsqrt(fmax(u1[0]*u1[0]+u1[1]*u1[1]+u1[2]*u1[2], 1e-300));
      double in2 = drsqrt(fmax(u2[0]*u2[0]+u2[1]*u2[1]+u2[2]*u2[2], 1e-300));
      #pragma unroll
      for (int i=0;i<3;i++){ u1[i]*=in1; u2[i]*=in2; }
      u3[0] = u1[1]*u2[2] - u1[2]*u2[1];
      u3[1] = u1[2]*u2[0] - u1[0]*u2[2];
      u3[2] = u1[0]*u2[1] - u1[1]*u2[0];
      double in3 = drsqrt(fmax(u3[0]*u3[0]+u3[1]*u3[1]+u3[2]*u3[2], 1e-300));
      #pragma unroll
      for (int i=0;i<3;i++) u3[i]*=in3;

      double detU = u1[0]*(u2[1]*u3[2]-u2[2]*u3[1])
                  - u1[1]*(u2[0]*u3[2]-u2[2]*u3[0])
                  + u1[2]*(u2[0]*u3[1]-u2[1]*u3[0]);
      double detV = v1[0]*(v2[1]*v3[2]-v2[2]*v3[1])
                  - v1[1]*(v2[0]*v3[2]-v2[2]*v3[0])
                  + v1[2]*(v2[0]*v3[1]-v2[1]*v3[0]);
      double dd = detU * detV;
      sSgn = (dd > 0.0) ? 1.0 : ((dd < 0.0) ? -1.0 : 0.0);
      #pragma unroll
      for (int i=0;i<3;i++) {
        sUV[i]    = u1[i];
        sUV[3+i]  = u2[i];
        sUV[6+i]  = u3[i];
        sUV[9+i]  = v1[i];
        sUV[12+i] = v2[i];
        sUV[15+i] = v3[i];
        st3[i] = (float)u3[i];
      }
    }
    __syncwarp();

    // parallel R1/R2 build (one element per lane)
    if (lane < 9) {
      int i = lane / 3, j = lane % 3;
      double u1i = sUV[i], u2i = sUV[3+i], u3i = sUV[6+i];
      double v1j = sUV[9+j], v2j = sUV[12+j], v3j = sUV[15+j];
      double sg = sSgn;
      double r1 =  u2i*v1j - u1i*v2j + u3i*v3j;
      double r2 = -u2i*v1j + u1i*v2j + u3i*v3j;
      sR1[lane] = (float)(r1*sg);
      sR2[lane] = (float)(r2*sg);
    }
  }
  __syncthreads();

  // ---- phase 3: cheirality (division-free sign tests) ----
  float R1[9], R2[9];
  #pragma unroll
  for (int i=0;i<9;i++){ R1[i]=sR1[i]; R2[i]=sR2[i]; }
  const float tv0=st3[0], tv1=st3[1], tv2=st3[2];

  float sc0=0.f, sc1=0.f, sc2=0.f, sc3=0.f;
  if (affine) {
    #pragma unroll
    for (int k = 0; k < NPTS/256; k++) {
      int n = tid + k*256;
      float4 q = sP[n];
      float w = sW[n];
      float bb = q.z*q.z + q.w*q.w + 1.0f;
      float bt = q.z*tv0 + q.w*tv1 + tv2;
      {
        float a0 = R1[0]*q.x + R1[1]*q.y + R1[2];
        float a1 = R1[3]*q.x + R1[4]*q.y + R1[5];
        float a2 = R1[6]*q.x + R1[7]*q.y + R1[8];
        float aa = a0*a0 + a1*a1 + a2*a2;
        float ab = a0*q.z + a1*q.w + a2;
        float at = a0*tv0 + a1*tv1 + a2*tv2;
        float det = aa*bb - ab*ab + 1e-9f;
        float n0 = -at*bb + ab*bt;
        float n1 = aa*bt - ab*at;
        bool dpn = det >= 0.f;
        if (dpn ? (n0 > 0.f && n1 > 0.f) : (n0 < 0.f && n1 < 0.f)) sc0 += w;
        if (dpn ? (n0 < 0.f && n1 < 0.f) : (n0 > 0.f && n1 > 0.f)) sc1 += w;
      }
      {
        float a0 = R2[0]*q.x + R2[1]*q.y + R2[2];
        float a1 = R2[3]*q.x + R2[4]*q.y + R2[5];
        float a2 = R2[6]*q.x + R2[7]*q.y + R2[8];
        float aa = a0*a0 + a1*a1 + a2*a2;
        float ab = a0*q.z + a1*q.w + a2;
        float at = a0*tv0 + a1*tv1 + a2*tv2;
        float det = aa*bb - ab*ab + 1e-9f;
        float n0 = -at*bb + ab*bt;
        float n1 = aa*bt - ab*at;
        bool dpn = det >= 0.f;
        if (dpn ? (n0 > 0.f && n1 > 0.f) : (n0 < 0.f && n1 < 0.f)) sc2 += w;
        if (dpn ? (n0 < 0.f && n1 < 0.f) : (n0 > 0.f && n1 > 0.f)) sc3 += w;
      }
    }
  } else {
    #pragma unroll
    for (int k = 0; k < NPTS/256; k++) {
      int n = tid + k*256;
      float2 p0 = kp0[n]; float2 p1 = kp1[n]; float w = wv[n];
      float x00 = Ki0[0]*p0.x + Ki0[1]*p0.y + Ki0[2];
      float x01 = Ki0[3]*p0.x + Ki0[4]*p0.y + Ki0[5];
      float x02 = Ki0[6]*p0.x + Ki0[7]*p0.y + Ki0[8];
      float x10 = Ki1[0]*p1.x + Ki1[1]*p1.y + Ki1[2];
      float x11 = Ki1[3]*p1.x + Ki1[4]*p1.y + Ki1[5];
      float x12 = Ki1[6]*p1.x + Ki1[7]*p1.y + Ki1[8];
      float bb = x10*x10 + x11*x11 + x12*x12;
      float bt = x10*tv0 + x11*tv1 + x12*tv2;
      {
        float a0 = R1[0]*x00 + R1[1]*x01 + R1[2]*x02;
        float a1 = R1[3]*x00 + R1[4]*x01 + R1[5]*x02;
        float a2 = R1[6]*x00 + R1[7]*x01 + R1[8]*x02;
        float aa = a0*a0 + a1*a1 + a2*a2;
        float ab = a0*x10 + a1*x11 + a2*x12;
        float at = a0*tv0 + a1*tv1 + a2*tv2;
        float det = aa*bb - ab*ab + 1e-9f;
        float n0 = -at*bb + ab*bt;
        float n1 = aa*bt - ab*at;
        bool dpn = det >= 0.f;
        if (dpn ? (n0 > 0.f && n1 > 0.f) : (n0 < 0.f && n1 < 0.f)) sc0 += w;
        if (dpn ? (n0 < 0.f && n1 < 0.f) : (n0 > 0.f && n1 > 0.f)) sc1 += w;
      }
      {
        float a0 = R2[0]*x00 + R2[1]*x01 + R2[2]*x02;
        float a1 = R2[3]*x00 + R2[4]*x01 + R2[5]*x02;
        float a2 = R2[6]*x00 + R2[7]*x01 + R2[8]*x02;
        float aa = a0*a0 + a1*a1 + a2*a2;
        float ab = a0*x10 + a1*x11 + a2*x12;
        float at = a0*tv0 + a1*tv1 + a2*tv2;
        float det = aa*bb - ab*ab + 1e-9f;
        float n0 = -at*bb + ab*bt;
        float n1 = aa*bt - ab*at;
        bool dpn = det >= 0.f;
        if (dpn ? (n0 > 0.f && n1 > 0.f) : (n0 < 0.f && n1 < 0.f)) sc2 += w;
        if (dpn ? (n0 < 0.f && n1 < 0.f) : (n0 > 0.f && n1 > 0.f)) sc3 += w;
      }
    }
  }
  #pragma unroll
  for (int off=16; off; off>>=1) {
    sc0 += __shfl_down_sync(FULLM, sc0, off);
    sc1 += __shfl_down_sync(FULLM, sc1, off);
    sc2 += __shfl_down_sync(FULLM, sc2, off);
    sc3 += __shfl_down_sync(FULLM, sc3, off);
  }
  if (lane == 0) { sred[warp][0]=sc0; sred[warp][1]=sc1; sred[warp][2]=sc2; sred[warp][3]=sc3; }
  __syncthreads();
  if (tid == 0) {
    float s0=0.f, s1=0.f, s2=0.f, s3=0.f;
    #pragma unroll
    for (int wp=0; wp<8; wp++){ s0+=sred[wp][0]; s1+=sred[wp][1]; s2+=sred[wp][2]; s3+=sred[wp][3]; }
    float bs = s0; int bi = 0;
    if (s1 > bs){ bs=s1; bi=1; }
    if (s2 > bs){ bs=s2; bi=2; }
    if (s3 > bs){ bs=s3; bi=3; }
    const float* R = (bi < 2) ? sR1 : sR2;
    float sgn = (bi & 1) ? -1.f : 1.f;
    float ts = tscale[b*2];
    float t0 = (sgn*st3[0])*ts;
    float t1 = (sgn*st3[1])*ts;
    float t2 = (sgn*st3[2])*ts;
    float* o = out + (size_t)b*32;
    o[0]=R[0]; o[1]=R[1]; o[2]=R[2];  o[3]=t0;
    o[4]=R[3]; o[5]=R[4]; o[6]=R[5];  o[7]=t1;
    o[8]=R[6]; o[9]=R[7]; o[10]=R[8]; o[11]=t2;
    o[12]=0.f; o[13]=0.f; o[14]=0.f; o[15]=1.f;
    float ti0 = -(R[0]*t0 + R[3]*t1 + R[6]*t2);
    float ti1 = -(R[1]*t0 + R[4]*t1 + R[7]*t2);
    float ti2 = -(R[2]*t0 + R[5]*t1 + R[8]*t2);
    o[16]=R[0]; o[17]=R[3]; o[18]=R[6]; o[19]=ti0;
    o[20]=R[1]; o[21]=R[4]; o[22]=R[7]; o[23]=ti1;
    o[24]=R[2]; o[25]=R[5]; o[26]=R[8]; o[27]=ti2;
    o[28]=0.f; o[29]=0.f; o[30]=0.f; o[31]=1.f;
  }
}

extern "C" void kernel_launch(void* const* d_in, const int* in_sizes, int n_in,
                              void* d_out, int out_size) {
  const float* kpts0  = (const float*)d_in[0];
  const float* kpts1  = (const float*)d_in[1];
  const float* conf   = (const float*)d_in[2];
  const float* tscale = (const float*)d_in[3];
  const float* Kmat   = (const float*)d_in[4];
  float* out = (float*)d_out;

  cudaFuncSetAttribute(k_fused, cudaFuncAttributeMaxDynamicSharedMemorySize, DYN_SMEM);
  k_fused<<<BATCH, 256, DYN_SMEM>>>(kpts0, kpts1, conf, tscale, Kmat, out);
}

// round 12
// speedup vs baseline: 1.7195x; 1.3347x over previous
#include <cuda_runtime.h>

#define BATCH 256
#define NPTS  4096
#define DYN_SMEM (NPTS*16 + NPTS*4)
#define FULLM 0xffffffffu

// ---------- fast double helpers: fp32 seed + 1 Newton step ----------
__device__ __forceinline__ double drecip(double x) {
  double y = (double)__fdividef(1.0f, (float)x);
  y = y * (2.0 - x * y);
  return y;
}
__device__ __forceinline__ double drsqrt(double x) {
  double y = (double)rsqrtf((float)x);
  y = y * (1.5 - 0.5 * x * y * y);
  return y;
}

__device__ __forceinline__ void inv3x3(const float* __restrict__ Km, float* __restrict__ out) {
  double a=Km[0], b=Km[1], c=Km[2], d=Km[3], e=Km[4], f=Km[5], g=Km[6], h=Km[7], i=Km[8];
  double det = a*(e*i - f*h) - b*(d*i - f*g) + c*(d*h - e*g);
  double inv = 1.0 / det;
  out[0]=(float)((e*i - f*h)*inv); out[1]=(float)((c*h - b*i)*inv); out[2]=(float)((b*f - c*e)*inv);
  out[3]=(float)((f*g - d*i)*inv); out[4]=(float)((a*i - c*g)*inv); out[5]=(float)((c*d - a*f)*inv);
  out[6]=(float)((d*h - e*g)*inv); out[7]=(float)((b*g - a*h)*inv); out[8]=(float)((a*e - b*d)*inv);
}

__device__ __forceinline__ int p2i(int a, int b) {
  int mn = a < b ? a : b, mx = a < b ? b : a;
  return mn*(5-mn)/2 + mx;
}

// fp32 Jacobi rotation on 3x3 symmetric (compile-time indices)
template<int P, int Q>
__device__ __forceinline__ void rot3f(float g[3][3], float Qm[3][3]) {
  constexpr int K2 = 3 - P - Q;
  float apq = g[P][Q];
  float app = g[P][P], aqq = g[Q][Q];
  if (fabsf(apq) <= 1e-12f * (fabsf(app) + fabsf(aqq))) return;
  float tau = __fdividef(aqq - app, 2.0f * apq);
  float tt = ((tau >= 0.0f) ? 1.0f : -1.0f) / (fabsf(tau) + sqrtf(1.0f + tau*tau));
  float c = rsqrtf(1.0f + tt*tt);
  float s = tt * c;
  float akp = g[K2][P], akq = g[K2][Q];
  float np = c*akp - s*akq, nq = s*akp + c*akq;
  g[K2][P] = np; g[P][K2] = np;
  g[K2][Q] = nq; g[Q][K2] = nq;
  g[P][P] = app - tt*apq;
  g[Q][Q] = aqq + tt*apq;
  g[P][Q] = 0.0f; g[Q][P] = 0.0f;
  #pragma unroll
  for (int r = 0; r < 3; r++) {
    float qp = Qm[r][P], qq = Qm[r][Q];
    Qm[r][P] = c*qp - s*qq;
    Qm[r][Q] = s*qp + c*qq;
  }
}

// ---------- single fused kernel: one block per batch ----------
__global__ __launch_bounds__(256, 2) void k_fused(const float* __restrict__ kpts0,
                                                  const float* __restrict__ kpts1,
                                                  const float* __restrict__ conf,
                                                  const float* __restrict__ tscale,
                                                  const float* __restrict__ Kmat,
                                                  float* __restrict__ out) {
  const int b = blockIdx.x;
  const int tid = threadIdx.x;
  const int warp = tid >> 5, lane = tid & 31;

  extern __shared__ char dyn[];
  float4* sP = (float4*)dyn;
  float*  sW = (float*)(dyn + NPTS*16);

  __shared__ float sKi[18];
  __shared__ float sred[8][36];
  __shared__ double sd[81];           // A floats, then D doubles
  __shared__ float sT[36];
  __shared__ float sR1[9], sR2[9], st3[3];
  __shared__ float scs[4], sss[4];
  __shared__ double sDinv[9], sSigma, sxd[9];
  __shared__ float sUVf[18], sSgnF;
  __shared__ int sIpiv[9], sPerm[9];
  __shared__ int sAffine;

  // ---- phase 0: K inverses ----
  if (tid == 0) {
    float ki0[9], ki1[9];
    inv3x3(Kmat + b*18, ki0);
    inv3x3(Kmat + b*18 + 9, ki1);
    #pragma unroll
    for (int i=0;i<9;i++) { sKi[i]=ki0[i]; sKi[9+i]=ki1[i]; }
    sAffine = (ki0[6]==0.f && ki0[7]==0.f && ki0[8]==1.f &&
               ki1[6]==0.f && ki1[7]==0.f && ki1[8]==1.f) ? 1 : 0;
  }
  __syncthreads();
  float Ki0[9], Ki1[9];
  #pragma unroll
  for (int i=0;i<9;i++){ Ki0[i]=sKi[i]; Ki1[i]=sKi[9+i]; }
  const int affine = sAffine;

  const float2* kp0 = (const float2*)(kpts0) + (size_t)b*NPTS;
  const float2* kp1 = (const float2*)(kpts1) + (size_t)b*NPTS;
  const float*  wv  = conf + (size_t)b*NPTS;

  // ---- phase 1: accumulate T[6][6] + stage coords (prefetch depth 4) ----
  {
    float acc[36];
    #pragma unroll
    for (int i=0;i<36;i++) acc[i]=0.f;

    float2 b0[4], b1[4]; float bwv[4];
    #pragma unroll
    for (int i=0;i<4;i++) {
      b0[i] = kp0[tid + i*256];
      b1[i] = kp1[tid + i*256];
      bwv[i] = wv[tid + i*256];
    }
    #pragma unroll
    for (int k = 0; k < NPTS/256; k++) {
      float2 c0 = b0[k & 3], c1 = b1[k & 3];
      float  cw = bwv[k & 3];
      if (k + 4 < NPTS/256) {
        b0[k & 3] = kp0[tid + (k+4)*256];
        b1[k & 3] = kp1[tid + (k+4)*256];
        bwv[k & 3] = wv[tid + (k+4)*256];
      }
      float x00 = Ki0[0]*c0.x + Ki0[1]*c0.y + Ki0[2];
      float x01 = Ki0[3]*c0.x + Ki0[4]*c0.y + Ki0[5];
      float x02 = Ki0[6]*c0.x + Ki0[7]*c0.y + Ki0[8];
      float x10 = Ki1[0]*c1.x + Ki1[1]*c1.y + Ki1[2];
      float x11 = Ki1[3]*c1.x + Ki1[4]*c1.y + Ki1[5];
      float x12 = Ki1[6]*c1.x + Ki1[7]*c1.y + Ki1[8];
      int n = tid + k*256;
      sP[n] = make_float4(x00, x01, x10, x11);
      sW[n] = cw;
      float s0a[6] = {x00*x00, x00*x01, x00*x02, x01*x01, x01*x02, x02*x02};
      float s1a[6] = {x10*x10, x10*x11, x10*x12, x11*x11, x11*x12, x12*x12};
      float ws1[6];
      #pragma unroll
      for (int a=0;a<6;a++) ws1[a] = cw*s1a[a];
      #pragma unroll
      for (int a=0;a<6;a++)
        #pragma unroll
        for (int bb2=0;bb2<6;bb2++)
          acc[a*6+bb2] = fmaf(ws1[a], s0a[bb2], acc[a*6+bb2]);
    }
    #pragma unroll
    for (int i=0;i<36;i++) {
      acc[i] += __shfl_down_sync(FULLM, acc[i], 16);
      acc[i] += __shfl_down_sync(FULLM, acc[i], 8);
      acc[i] += __shfl_down_sync(FULLM, acc[i], 4);
      acc[i] += __shfl_down_sync(FULLM, acc[i], 2);
      acc[i] += __shfl_down_sync(FULLM, acc[i], 1);
    }
    if (lane == 0) {
      #pragma unroll
      for (int i=0;i<36;i++) sred[warp][i] = acc[i];
    }
    __syncthreads();
    if (tid < 36) {
      float s = 0.f;
      #pragma unroll
      for (int wp=0; wp<8; wp++) s += sred[wp][tid];
      sT[tid] = s;
    }
    __syncthreads();
  }

  // ---- phase 2: eigensolve + essential decomposition (warp 0) ----
  if (warp == 0) {
    float* A = (float*)&sd[0];   // 81 floats (no V)

    if (lane < 9) {
      const int i0 = lane / 3, j0 = lane % 3;
      #pragma unroll
      for (int j = 0; j < 9; j++)
        A[lane*9+j] = sT[p2i(i0, j/3)*6 + p2i(j0, j%3)];
    }
    __syncwarp();

    // Phase A: parallel-ordered fp32 Jacobi, 3 sweeps, sigma only
    for (int sweep = 0; sweep < 3; sweep++) {
      for (int r = 0; r < 9; r++) {
        const int bye = (5 * ((2*r) % 9)) % 9;
        if (lane < 4) {
          int d = lane + 1;
          int a = (bye + d) % 9;
          int bq = (bye + 9 - d) % 9;
          int p = a < bq ? a : bq;
          int q = a < bq ? bq : a;
          float apq = A[p*9+q], app = A[p*9+p], aqq = A[q*9+q];
          float c = 1.0f, s = 0.0f;
          if (fabsf(apq) > 6e-8f * (fabsf(app) + fabsf(aqq))) {
            float tau = __fdividef(aqq - app, 2.0f * apq);
            float t = ((tau >= 0.0f) ? 1.0f : -1.0f) / (fabsf(tau) + sqrtf(1.0f + tau*tau));
            c = rsqrtf(1.0f + t*t);
            s = t * c;
          }
          scs[lane] = c; sss[lane] = s;
        }
        __syncwarp();
        float cr[4], sr[4];
        int pr[4], qr[4];
        #pragma unroll
        for (int d = 0; d < 4; d++) {
          cr[d] = scs[d]; sr[d] = sss[d];
          int a = (bye + d + 1) % 9;
          int bq = (bye + 8 - d) % 9;
          pr[d] = a < bq ? a : bq;
          qr[d] = a < bq ? bq : a;
        }
        if (lane < 9) {
          #pragma unroll
          for (int d = 0; d < 4; d++) {
            int p = pr[d], q = qr[d];
            float vp = A[lane*9+p], vq = A[lane*9+q];
            A[lane*9+p] = cr[d]*vp - sr[d]*vq;
            A[lane*9+q] = sr[d]*vp + cr[d]*vq;
          }
        }
        __syncwarp();
        if (lane < 9) {
          #pragma unroll
          for (int d = 0; d < 4; d++) {
            int p = pr[d], q = qr[d];
            float vp = A[p*9+lane], vq = A[q*9+lane];
            A[p*9+lane] = cr[d]*vp - sr[d]*vq;
            A[q*9+lane] = sr[d]*vp + cr[d]*vq;
          }
        }
        __syncwarp();
      }
    }

    if (lane == 0) {
      float mv = A[0];
      #pragma unroll
      for (int k=1;k<9;k++) mv = fminf(mv, A[k*9+k]);
      sSigma = (double)mv;
    }
    __syncwarp();
    double sigma = sSigma;

    // build D = M - sigma*I in parallel (overwrite A region)
    double* D = &sd[0];
    if (lane < 9) {
      int i0 = lane/3, j0 = lane%3;
      #pragma unroll
      for (int j=0;j<9;j++)
        D[lane*9+j] = (double)sT[p2i(i0, j/3)*6 + p2i(j0, j%3)];
      D[lane*9+lane] -= sigma;
    }
    __syncwarp();

    // parallel LU with partial pivoting (rows across lanes)
    for (int k=0;k<9;k++) {
      if (lane == 0) {
        int p = k; double mx = fabs(D[k*9+k]);
        for (int i=k+1;i<9;i++){ double v = fabs(D[i*9+k]); if (v > mx){ mx=v; p=i; } }
        sIpiv[k] = p;
      }
      __syncwarp();
      int p = sIpiv[k];
      if (p != k && lane < 9) {
        double t = D[k*9+lane]; D[k*9+lane] = D[p*9+lane]; D[p*9+lane] = t;
      }
      __syncwarp();
      double pv = D[k*9+k];
      if (fabs(pv) < 1e-30) pv = (pv >= 0.0) ? 1e-30 : -1e-30;
      double ipv = drecip(pv);
      if (lane == 0) sDinv[k] = ipv;
      if (lane > k && lane < 9) {
        double l = D[lane*9+k] * ipv;
        D[lane*9+k] = l;
        for (int j=k+1;j<9;j++) D[lane*9+j] -= l * D[k*9+j];
      }
      __syncwarp();
    }

    // permutation map
    if (lane == 0) {
      int idx[9];
      #pragma unroll
      for (int i=0;i<9;i++) idx[i]=i;
      for (int k=0;k<9;k++){ int p=sIpiv[k]; int t=idx[k]; idx[k]=idx[p]; idx[p]=t; }
      #pragma unroll
      for (int i=0;i<9;i++) sPerm[i]=idx[i];
    }
    __syncwarp();

    // per-lane row preload
    double row[9]; double dinv_l = 1.0; int permL = 0;
    if (lane < 9) {
      #pragma unroll
      for (int j=0;j<9;j++) row[j] = D[lane*9+j];
      dinv_l = sDinv[lane];
      permL = sPerm[lane];
    }

    // lane-parallel inverse iteration: 3 solves from ones vector
    double rv = 1.0;
    for (int it=0; it<3; it++) {
      if (lane < 9) sxd[lane] = rv;
      __syncwarp();
      if (lane < 9) rv = sxd[permL];
      __syncwarp();
      #pragma unroll
      for (int j=0;j<8;j++) {
        double yj = __shfl_sync(FULLM, rv, j);
        if (lane > j && lane < 9) rv -= row[j]*yj;
      }
      #pragma unroll
      for (int j=8;j>=0;j--) {
        if (lane == j) rv *= dinv_l;
        double xj = __shfl_sync(FULLM, rv, j);
        if (lane < j) rv -= row[j]*xj;
      }
      double c2 = (lane < 9) ? rv*rv : 0.0;
      #pragma unroll
      for (int off=16; off; off>>=1) c2 += __shfl_xor_sync(FULLM, c2, off);
      rv *= drsqrt(c2);
    }
    if (lane < 9) sxd[lane] = rv;
    __syncwarp();

    // lane 0: 3x3 SVD of E in fp32 (R = UWV^T invariant under sigma1~sigma2 ambiguity)
    if (lane == 0) {
      float e[9];
      #pragma unroll
      for (int k=0;k<9;k++) e[k] = (float)sxd[k];

      float G3[3][3];
      #pragma unroll
      for (int i=0;i<3;i++)
        #pragma unroll
        for (int j=0;j<3;j++)
          G3[i][j] = e[0+i]*e[0+j] + e[3+i]*e[3+j] + e[6+i]*e[6+j];

      float Qm[3][3] = {{1.f,0.f,0.f},{0.f,1.f,0.f},{0.f,0.f,1.f}};
      #pragma unroll
      for (int sw=0; sw<4; sw++) { rot3f<0,1>(G3,Qm); rot3f<0,2>(G3,Qm); rot3f<1,2>(G3,Qm); }

      float lam0=G3[0][0], lam1=G3[1][1], lam2=G3[2][2];
      int o0, o1, o2;
      if (lam0 >= lam1) {
        if (lam0 >= lam2) { o0=0; if (lam1>=lam2){o1=1;o2=2;} else {o1=2;o2=1;} }
        else              { o0=2; o1=0; o2=1; }
      } else {
        if (lam1 >= lam2) { o0=1; if (lam0>=lam2){o1=0;o2=2;} else {o1=2;o2=0;} }
        else              { o0=2; o1=1; o2=0; }
      }
      float v1[3] = {Qm[0][o0], Qm[1][o0], Qm[2][o0]};
      float v2[3] = {Qm[0][o1], Qm[1][o1], Qm[2][o1]};
      float v3[3] = {Qm[0][o2], Qm[1][o2], Qm[2][o2]};

      float u1[3], u2[3], u3[3];
      #pragma unroll
      for (int i=0;i<3;i++) {
        u1[i] = e[3*i+0]*v1[0] + e[3*i+1]*v1[1] + e[3*i+2]*v1[2];
        u2[i] = e[3*i+0]*v2[0] + e[3*i+1]*v2[1] + e[3*i+2]*v2[2];
      }
      float in1 = rsqrtf(fmaxf(u1[0]*u1[0]+u1[1]*u1[1]+u1[2]*u1[2], 1e-30f));
      float in2 = rsqrtf(fmaxf(u2[0]*u2[0]+u2[1]*u2[1]+u2[2]*u2[2], 1e-30f));
      #pragma unroll
      for (int i=0;i<3;i++){ u1[i]*=in1; u2[i]*=in2; }
      u3[0] = u1[1]*u2[2] - u1[2]*u2[1];
      u3[1] = u1[2]*u2[0] - u1[0]*u2[2];
      u3[2] = u1[0]*u2[1] - u1[1]*u2[0];
      float in3 = rsqrtf(fmaxf(u3[0]*u3[0]+u3[1]*u3[1]+u3[2]*u3[2], 1e-30f));
      #pragma unroll
      for (int i=0;i<3;i++) u3[i]*=in3;

      float detU = u1[0]*(u2[1]*u3[2]-u2[2]*u3[1])
                 - u1[1]*(u2[0]*u3[2]-u2[2]*u3[0])
                 + u1[2]*(u2[0]*u3[1]-u2[1]*u3[0]);
      float detV = v1[0]*(v2[1]*v3[2]-v2[2]*v3[1])
                 - v1[1]*(v2[0]*v3[2]-v2[2]*v3[0])
                 + v1[2]*(v2[0]*v3[1]-v2[1]*v3[0]);
      float dd = detU * detV;
      sSgnF = (dd > 0.0f) ? 1.0f : ((dd < 0.0f) ? -1.0f : 0.0f);
      #pragma unroll
      for (int i=0;i<3;i++) {
        sUVf[i]    = u1[i];
        sUVf[3+i]  = u2[i];
        sUVf[6+i]  = u3[i];
        sUVf[9+i]  = v1[i];
        sUVf[12+i] = v2[i];
        sUVf[15+i] = v3[i];
        st3[i] = u3[i];
      }
    }
    __syncwarp();

    // parallel R1/R2 build (one element per lane, fp32)
    if (lane < 9) {
      int i = lane / 3, j = lane % 3;
      float u1i = sUVf[i], u2i = sUVf[3+i], u3i = sUVf[6+i];
      float v1j = sUVf[9+j], v2j = sUVf[12+j], v3j = sUVf[15+j];
      float sg = sSgnF;
      sR1[lane] = ( u2i*v1j - u1i*v2j + u3i*v3j)*sg;
      sR2[lane] = (-u2i*v1j + u1i*v2j + u3i*v3j)*sg;
    }
  }
  __syncthreads();

  // ---- phase 3: cheirality (division-free sign tests) ----
  float R1[9], R2[9];
  #pragma unroll
  for (int i=0;i<9;i++){ R1[i]=sR1[i]; R2[i]=sR2[i]; }
  const float tv0=st3[0], tv1=st3[1], tv2=st3[2];

  float sc0=0.f, sc1=0.f, sc2=0.f, sc3=0.f;
  if (affine) {
    #pragma unroll
    for (int k = 0; k < NPTS/256; k++) {
      int n = tid + k*256;
      float4 q = sP[n];
      float w = sW[n];
      float bb = q.z*q.z + q.w*q.w + 1.0f;
      float bt = q.z*tv0 + q.w*tv1 + tv2;
      {
        float a0 = R1[0]*q.x + R1[1]*q.y + R1[2];
        float a1 = R1[3]*q.x + R1[4]*q.y + R1[5];
        float a2 = R1[6]*q.x + R1[7]*q.y + R1[8];
        float aa = a0*a0 + a1*a1 + a2*a2;
        float ab = a0*q.z + a1*q.w + a2;
        float at = a0*tv0 + a1*tv1 + a2*tv2;
        float det = aa*bb - ab*ab + 1e-9f;
        float n0 = -at*bb + ab*bt;
        float n1 = aa*bt - ab*at;
        bool dpn = det >= 0.f;
        if (dpn ? (n0 > 0.f && n1 > 0.f) : (n0 < 0.f && n1 < 0.f)) sc0 += w;
        if (dpn ? (n0 < 0.f && n1 < 0.f) : (n0 > 0.f && n1 > 0.f)) sc1 += w;
      }
      {
        float a0 = R2[0]*q.x + R2[1]*q.y + R2[2];
        float a1 = R2[3]*q.x + R2[4]*q.y + R2[5];
        float a2 = R2[6]*q.x + R2[7]*q.y + R2[8];
        float aa = a0*a0 + a1*a1 + a2*a2;
        float ab = a0*q.z + a1*q.w + a2;
        float at = a0*tv0 + a1*tv1 + a2*tv2;
        float det = aa*bb - ab*ab + 1e-9f;
        float n0 = -at*bb + ab*bt;
        float n1 = aa*bt - ab*at;
        bool dpn = det >= 0.f;
        if (dpn ? (n0 > 0.f && n1 > 0.f) : (n0 < 0.f && n1 < 0.f)) sc2 += w;
        if (dpn ? (n0 < 0.f && n1 < 0.f) : (n0 > 0.f && n1 > 0.f)) sc3 += w;
      }
    }
  } else {
    #pragma unroll
    for (int k = 0; k < NPTS/256; k++) {
      int n = tid + k*256;
      float2 p0 = kp0[n]; float2 p1 = kp1[n]; float w = wv[n];
      float x00 = Ki0[0]*p0.x + Ki0[1]*p0.y + Ki0[2];
      float x01 = Ki0[3]*p0.x + Ki0[4]*p0.y + Ki0[5];
      float x02 = Ki0[6]*p0.x + Ki0[7]*p0.y + Ki0[8];
      float x10 = Ki1[0]*p1.x + Ki1[1]*p1.y + Ki1[2];
      float x11 = Ki1[3]*p1.x + Ki1[4]*p1.y + Ki1[5];
      float x12 = Ki1[6]*p1.x + Ki1[7]*p1.y + Ki1[8];
      float bb = x10*x10 + x11*x11 + x12*x12;
      float bt = x10*tv0 + x11*tv1 + x12*tv2;
      {
        float a0 = R1[0]*x00 + R1[1]*x01 + R1[2]*x02;
        float a1 = R1[3]*x00 + R1[4]*x01 + R1[5]*x02;
        float a2 = R1[6]*x00 + R1[7]*x01 + R1[8]*x02;
        float aa = a0*a0 + a1*a1 + a2*a2;
        float ab = a0*x10 + a1*x11 + a2*x12;
        float at = a0*tv0 + a1*tv1 + a2*tv2;
        float det = aa*bb - ab*ab + 1e-9f;
        float n0 = -at*bb + ab*bt;
        float n1 = aa*bt - ab*at;
        bool dpn = det >= 0.f;
        if (dpn ? (n0 > 0.f && n1 > 0.f) : (n0 < 0.f && n1 < 0.f)) sc0 += w;
        if (dpn ? (n0 < 0.f && n1 < 0.f) : (n0 > 0.f && n1 > 0.f)) sc1 += w;
      }
      {
        float a0 = R2[0]*x00 + R2[1]*x01 + R2[2]*x02;
        float a1 = R2[3]*x00 + R2[4]*x01 + R2[5]*x02;
        float a2 = R2[6]*x00 + R2[7]*x01 + R2[8]*x02;
        float aa = a0*a0 + a1*a1 + a2*a2;
        float ab = a0*x10 + a1*x11 + a2*x12;
        float at = a0*tv0 + a1*tv1 + a2*tv2;
        float det = aa*bb - ab*ab + 1e-9f;
        float n0 = -at*bb + ab*bt;
        float n1 = aa*bt - ab*at;
        bool dpn = det >= 0.f;
        if (dpn ? (n0 > 0.f && n1 > 0.f) : (n0 < 0.f && n1 < 0.f)) sc2 += w;
        if (dpn ? (n0 < 0.f && n1 < 0.f) : (n0 > 0.f && n1 > 0.f)) sc3 += w;
      }
    }
  }
  #pragma unroll
  for (int off=16; off; off>>=1) {
    sc0 += __shfl_down_sync(FULLM, sc0, off);
    sc1 += __shfl_down_sync(FULLM, sc1, off);
    sc2 += __shfl_down_sync(FULLM, sc2, off);
    sc3 += __shfl_down_sync(FULLM, sc3, off);
  }
  if (lane == 0) { sred[warp][0]=sc0; sred[warp][1]=sc1; sred[warp][2]=sc2; sred[warp][3]=sc3; }
  __syncthreads();
  if (tid == 0) {
    float s0=0.f, s1=0.f, s2=0.f, s3=0.f;
    #pragma unroll
    for (int wp=0; wp<8; wp++){ s0+=sred[wp][0]; s1+=sred[wp][1]; s2+=sred[wp][2]; s3+=sred[wp][3]; }
    float bs = s0; int bi = 0;
    if (s1 > bs){ bs=s1; bi=1; }
    if (s2 > bs){ bs=s2; bi=2; }
    if (s3 > bs){ bs=s3; bi=3; }
    const float* R = (bi < 2) ? sR1 : sR2;
    float sgn = (bi & 1) ? -1.f : 1.f;
    float ts = tscale[b*2];
    float t0 = (sgn*st3[0])*ts;
    float t1 = (sgn*st3[1])*ts;
    float t2 = (sgn*st3[2])*ts;
    float* o = out + (size_t)b*32;
    o[0]=R[0]; o[1]=R[1]; o[2]=R[2];  o[3]=t0;
    o[4]=R[3]; o[5]=R[4]; o[6]=R[5];  o[7]=t1;
    o[8]=R[6]; o[9]=R[7]; o[10]=R[8]; o[11]=t2;
    o[12]=0.f; o[13]=0.f; o[14]=0.f; o[15]=1.f;
    float ti0 = -(R[0]*t0 + R[3]*t1 + R[6]*t2);
    float ti1 = -(R[1]*t0 + R[4]*t1 + R[7]*t2);
    float ti2 = -(R[2]*t0 + R[5]*t1 + R[8]*t2);
    o[16]=R[0]; o[17]=R[3]; o[18]=R[6]; o[19]=ti0;
    o[20]=R[1]; o[21]=R[4]; o[22]=R[7]; o[23]=ti1;
    o[24]=R[2]; o[25]=R[5]; o[26]=R[8]; o[27]=ti2;
    o[28]=0.f; o[29]=0.f; o[30]=0.f; o[31]=1.f;
  }
}

extern "C" void kernel_launch(void* const* d_in, const int* in_sizes, int n_in,
                              void* d_out, int out_size) {
  const float* kpts0  = (const float*)d_in[0];
  const float* kpts1  = (const float*)d_in[1];
  const float* conf   = (const float*)d_in[2];
  const float* tscale = (const float*)d_in[3];
  const float* Kmat   = (const float*)d_in[4];
  float* out = (float*)d_out;

  cudaFuncSetAttribute(k_fused, cudaFuncAttributeMaxDynamicSharedMemorySize, DYN_SMEM);
  k_fused<<<BATCH, 256, DYN_SMEM>>>(kpts0, kpts1, conf, tscale, Kmat, out);
}

// round 13
// speedup vs baseline: 1.7876x; 1.0396x over previous
#include <cuda_runtime.h>

#define BATCH 256
#define NPTS  4096
#define DYN_SMEM (NPTS*16 + NPTS*4)
#define FULLM 0xffffffffu

// ---------- fast double helpers: fp32 seed + 1 Newton step ----------
__device__ __forceinline__ double drecip(double x) {
  double y = (double)__fdividef(1.0f, (float)x);
  y = y * (2.0 - x * y);
  return y;
}
__device__ __forceinline__ double drsqrt(double x) {
  double y = (double)rsqrtf((float)x);
  y = y * (1.5 - 0.5 * x * y * y);
  return y;
}

__device__ __forceinline__ void inv3x3(const float* __restrict__ Km, float* __restrict__ out) {
  double a=Km[0], b=Km[1], c=Km[2], d=Km[3], e=Km[4], f=Km[5], g=Km[6], h=Km[7], i=Km[8];
  double det = a*(e*i - f*h) - b*(d*i - f*g) + c*(d*h - e*g);
  double inv = 1.0 / det;
  out[0]=(float)((e*i - f*h)*inv); out[1]=(float)((c*h - b*i)*inv); out[2]=(float)((b*f - c*e)*inv);
  out[3]=(float)((f*g - d*i)*inv); out[4]=(float)((a*i - c*g)*inv); out[5]=(float)((c*d - a*f)*inv);
  out[6]=(float)((d*h - e*g)*inv); out[7]=(float)((b*g - a*h)*inv); out[8]=(float)((a*e - b*d)*inv);
}

__device__ __forceinline__ int p2i(int a, int b) {
  int mn = a < b ? a : b, mx = a < b ? b : a;
  return mn*(5-mn)/2 + mx;
}

// fp32 Jacobi rotation on 3x3 symmetric (compile-time indices)
template<int P, int Q>
__device__ __forceinline__ void rot3f(float g[3][3], float Qm[3][3]) {
  constexpr int K2 = 3 - P - Q;
  float apq = g[P][Q];
  float app = g[P][P], aqq = g[Q][Q];
  if (fabsf(apq) <= 1e-12f * (fabsf(app) + fabsf(aqq))) return;
  float tau = __fdividef(aqq - app, 2.0f * apq);
  float tt = ((tau >= 0.0f) ? 1.0f : -1.0f) / (fabsf(tau) + sqrtf(1.0f + tau*tau));
  float c = rsqrtf(1.0f + tt*tt);
  float s = tt * c;
  float akp = g[K2][P], akq = g[K2][Q];
  float np = c*akp - s*akq, nq = s*akp + c*akq;
  g[K2][P] = np; g[P][K2] = np;
  g[K2][Q] = nq; g[Q][K2] = nq;
  g[P][P] = app - tt*apq;
  g[Q][Q] = aqq + tt*apq;
  g[P][Q] = 0.0f; g[Q][P] = 0.0f;
  #pragma unroll
  for (int r = 0; r < 3; r++) {
    float qp = Qm[r][P], qq = Qm[r][Q];
    Qm[r][P] = c*qp - s*qq;
    Qm[r][Q] = s*qp + c*qq;
  }
}

// ---------- single fused kernel: one block per batch ----------
__global__ __launch_bounds__(256, 2) void k_fused(const float* __restrict__ kpts0,
                                                  const float* __restrict__ kpts1,
                                                  const float* __restrict__ conf,
                                                  const float* __restrict__ tscale,
                                                  const float* __restrict__ Kmat,
                                                  float* __restrict__ out) {
  const int b = blockIdx.x;
  const int tid = threadIdx.x;
  const int warp = tid >> 5, lane = tid & 31;

  extern __shared__ char dyn[];
  float4* sP = (float4*)dyn;
  float*  sW = (float*)(dyn + NPTS*16);

  __shared__ float sKi[18];
  __shared__ float sred[8][36];
  __shared__ double sd[81];           // A floats, then D doubles
  __shared__ float sT[36];
  __shared__ float sR1[9], st3[3];
  __shared__ float scs[4], sss[4];
  __shared__ double sDinv[9], sSigma, sxd[9];
  __shared__ float sUVf[18], sSgnF;
  __shared__ int sIpiv[9], sPerm[9];
  __shared__ int sAffine;

  // ---- phase 0: K inverses ----
  if (tid == 0) {
    float ki0[9], ki1[9];
    inv3x3(Kmat + b*18, ki0);
    inv3x3(Kmat + b*18 + 9, ki1);
    #pragma unroll
    for (int i=0;i<9;i++) { sKi[i]=ki0[i]; sKi[9+i]=ki1[i]; }
    sAffine = (ki0[6]==0.f && ki0[7]==0.f && ki0[8]==1.f &&
               ki1[6]==0.f && ki1[7]==0.f && ki1[8]==1.f) ? 1 : 0;
  }
  __syncthreads();
  float Ki0[9], Ki1[9];
  #pragma unroll
  for (int i=0;i<9;i++){ Ki0[i]=sKi[i]; Ki1[i]=sKi[9+i]; }
  const int affine = sAffine;

  const float2* kp0 = (const float2*)(kpts0) + (size_t)b*NPTS;
  const float2* kp1 = (const float2*)(kpts1) + (size_t)b*NPTS;
  const float*  wv  = conf + (size_t)b*NPTS;

  // ---- phase 1: accumulate T[6][6] + stage coords (prefetch depth 4) ----
  {
    float acc[36];
    #pragma unroll
    for (int i=0;i<36;i++) acc[i]=0.f;

    float2 b0[4], b1[4]; float bwv[4];
    #pragma unroll
    for (int i=0;i<4;i++) {
      b0[i] = kp0[tid + i*256];
      b1[i] = kp1[tid + i*256];
      bwv[i] = wv[tid + i*256];
    }
    #pragma unroll
    for (int k = 0; k < NPTS/256; k++) {
      float2 c0 = b0[k & 3], c1 = b1[k & 3];
      float  cw = bwv[k & 3];
      if (k + 4 < NPTS/256) {
        b0[k & 3] = kp0[tid + (k+4)*256];
        b1[k & 3] = kp1[tid + (k+4)*256];
        bwv[k & 3] = wv[tid + (k+4)*256];
      }
      float x00 = Ki0[0]*c0.x + Ki0[1]*c0.y + Ki0[2];
      float x01 = Ki0[3]*c0.x + Ki0[4]*c0.y + Ki0[5];
      float x02 = Ki0[6]*c0.x + Ki0[7]*c0.y + Ki0[8];
      float x10 = Ki1[0]*c1.x + Ki1[1]*c1.y + Ki1[2];
      float x11 = Ki1[3]*c1.x + Ki1[4]*c1.y + Ki1[5];
      float x12 = Ki1[6]*c1.x + Ki1[7]*c1.y + Ki1[8];
      int n = tid + k*256;
      sP[n] = make_float4(x00, x01, x10, x11);
      sW[n] = cw;
      float s0a[6] = {x00*x00, x00*x01, x00*x02, x01*x01, x01*x02, x02*x02};
      float s1a[6] = {x10*x10, x10*x11, x10*x12, x11*x11, x11*x12, x12*x12};
      float ws1[6];
      #pragma unroll
      for (int a=0;a<6;a++) ws1[a] = cw*s1a[a];
      #pragma unroll
      for (int a=0;a<6;a++)
        #pragma unroll
        for (int bb2=0;bb2<6;bb2++)
          acc[a*6+bb2] = fmaf(ws1[a], s0a[bb2], acc[a*6+bb2]);
    }
    #pragma unroll
    for (int i=0;i<36;i++) {
      acc[i] += __shfl_down_sync(FULLM, acc[i], 16);
      acc[i] += __shfl_down_sync(FULLM, acc[i], 8);
      acc[i] += __shfl_down_sync(FULLM, acc[i], 4);
      acc[i] += __shfl_down_sync(FULLM, acc[i], 2);
      acc[i] += __shfl_down_sync(FULLM, acc[i], 1);
    }
    if (lane == 0) {
      #pragma unroll
      for (int i=0;i<36;i++) sred[warp][i] = acc[i];
    }
    __syncthreads();
    if (tid < 36) {
      float s = 0.f;
      #pragma unroll
      for (int wp=0; wp<8; wp++) s += sred[wp][tid];
      sT[tid] = s;
    }
    __syncthreads();
  }

  // ---- phase 2: eigensolve + essential decomposition (warp 0) ----
  if (warp == 0) {
    float* A = (float*)&sd[0];   // 81 floats

    if (lane < 9) {
      const int i0 = lane / 3, j0 = lane % 3;
      #pragma unroll
      for (int j = 0; j < 9; j++)
        A[lane*9+j] = sT[p2i(i0, j/3)*6 + p2i(j0, j%3)];
    }
    __syncwarp();

    // Phase A: parallel-ordered fp32 Jacobi, 3 sweeps, sigma only
    for (int sweep = 0; sweep < 3; sweep++) {
      for (int r = 0; r < 9; r++) {
        const int bye = (5 * ((2*r) % 9)) % 9;
        if (lane < 4) {
          int d = lane + 1;
          int a = (bye + d) % 9;
          int bq = (bye + 9 - d) % 9;
          int p = a < bq ? a : bq;
          int q = a < bq ? bq : a;
          float apq = A[p*9+q], app = A[p*9+p], aqq = A[q*9+q];
          float c = 1.0f, s = 0.0f;
          if (fabsf(apq) > 6e-8f * (fabsf(app) + fabsf(aqq))) {
            float tau = __fdividef(aqq - app, 2.0f * apq);
            float t = ((tau >= 0.0f) ? 1.0f : -1.0f) / (fabsf(tau) + sqrtf(1.0f + tau*tau));
            c = rsqrtf(1.0f + t*t);
            s = t * c;
          }
          scs[lane] = c; sss[lane] = s;
        }
        __syncwarp();
        float cr[4], sr[4];
        int pr[4], qr[4];
        #pragma unroll
        for (int d = 0; d < 4; d++) {
          cr[d] = scs[d]; sr[d] = sss[d];
          int a = (bye + d + 1) % 9;
          int bq = (bye + 8 - d) % 9;
          pr[d] = a < bq ? a : bq;
          qr[d] = a < bq ? bq : a;
        }
        if (lane < 9) {
          #pragma unroll
          for (int d = 0; d < 4; d++) {
            int p = pr[d], q = qr[d];
            float vp = A[lane*9+p], vq = A[lane*9+q];
            A[lane*9+p] = cr[d]*vp - sr[d]*vq;
            A[lane*9+q] = sr[d]*vp + cr[d]*vq;
          }
        }
        __syncwarp();
        if (lane < 9) {
          #pragma unroll
          for (int d = 0; d < 4; d++) {
            int p = pr[d], q = qr[d];
            float vp = A[p*9+lane], vq = A[q*9+lane];
            A[p*9+lane] = cr[d]*vp - sr[d]*vq;
            A[q*9+lane] = sr[d]*vp + cr[d]*vq;
          }
        }
        __syncwarp();
      }
    }

    if (lane == 0) {
      float mv = A[0];
      #pragma unroll
      for (int k=1;k<9;k++) mv = fminf(mv, A[k*9+k]);
      sSigma = (double)mv;
    }
    __syncwarp();
    double sigma = sSigma;

    // build D = M - sigma*I in parallel (overwrite A region)
    double* D = &sd[0];
    if (lane < 9) {
      int i0 = lane/3, j0 = lane%3;
      #pragma unroll
      for (int j=0;j<9;j++)
        D[lane*9+j] = (double)sT[p2i(i0, j/3)*6 + p2i(j0, j%3)];
      D[lane*9+lane] -= sigma;
    }
    __syncwarp();

    // parallel LU with partial pivoting; parallel (shuffle) pivot search
    for (int k=0;k<9;k++) {
      // pivot argmax over rows k..8 (first-max tie-break = smallest index)
      double av = (lane < 9 && lane >= k) ? fabs(D[lane*9+k]) : -1.0;
      int ai = lane;
      #pragma unroll
      for (int off=16; off; off>>=1) {
        double ov = __shfl_xor_sync(FULLM, av, off);
        int oi = __shfl_xor_sync(FULLM, ai, off);
        if (ov > av || (ov == av && oi < ai)) { av = ov; ai = oi; }
      }
      int p = ai;
      if (lane == 0) sIpiv[k] = p;
      if (p != k && lane < 9) {
        double t = D[k*9+lane]; D[k*9+lane] = D[p*9+lane]; D[p*9+lane] = t;
      }
      __syncwarp();
      double pv = D[k*9+k];
      if (fabs(pv) < 1e-30) pv = (pv >= 0.0) ? 1e-30 : -1e-30;
      double ipv = drecip(pv);
      if (lane == 0) sDinv[k] = ipv;
      if (lane > k && lane < 9) {
        double l = D[lane*9+k] * ipv;
        D[lane*9+k] = l;
        for (int j=k+1;j<9;j++) D[lane*9+j] -= l * D[k*9+j];
      }
      __syncwarp();
    }

    // permutation map
    if (lane == 0) {
      int idx[9];
      #pragma unroll
      for (int i=0;i<9;i++) idx[i]=i;
      for (int k=0;k<9;k++){ int p=sIpiv[k]; int t=idx[k]; idx[k]=idx[p]; idx[p]=t; }
      #pragma unroll
      for (int i=0;i<9;i++) sPerm[i]=idx[i];
    }
    __syncwarp();

    // per-lane row preload
    double row[9]; double dinv_l = 1.0; int permL = 0;
    if (lane < 9) {
      #pragma unroll
      for (int j=0;j<9;j++) row[j] = D[lane*9+j];
      dinv_l = sDinv[lane];
      permL = sPerm[lane];
    }

    // lane-parallel inverse iteration: 2 solves from ones vector
    double rv = 1.0;
    for (int it=0; it<2; it++) {
      if (lane < 9) sxd[lane] = rv;
      __syncwarp();
      if (lane < 9) rv = sxd[permL];
      __syncwarp();
      #pragma unroll
      for (int j=0;j<8;j++) {
        double yj = __shfl_sync(FULLM, rv, j);
        if (lane > j && lane < 9) rv -= row[j]*yj;
      }
      #pragma unroll
      for (int j=8;j>=0;j--) {
        if (lane == j) rv *= dinv_l;
        double xj = __shfl_sync(FULLM, rv, j);
        if (lane < j) rv -= row[j]*xj;
      }
      double c2 = (lane < 9) ? rv*rv : 0.0;
      #pragma unroll
      for (int off=16; off; off>>=1) c2 += __shfl_xor_sync(FULLM, c2, off);
      rv *= drsqrt(c2);
    }
    if (lane < 9) sxd[lane] = rv;
    __syncwarp();

    // lane 0: 3x3 SVD of E in fp32
    if (lane == 0) {
      float e[9];
      #pragma unroll
      for (int k=0;k<9;k++) e[k] = (float)sxd[k];

      float G3[3][3];
      #pragma unroll
      for (int i=0;i<3;i++)
        #pragma unroll
        for (int j=0;j<3;j++)
          G3[i][j] = e[0+i]*e[0+j] + e[3+i]*e[3+j] + e[6+i]*e[6+j];

      float Qm[3][3] = {{1.f,0.f,0.f},{0.f,1.f,0.f},{0.f,0.f,1.f}};
      #pragma unroll
      for (int sw=0; sw<4; sw++) { rot3f<0,1>(G3,Qm); rot3f<0,2>(G3,Qm); rot3f<1,2>(G3,Qm); }

      float lam0=G3[0][0], lam1=G3[1][1], lam2=G3[2][2];
      int o0, o1, o2;
      if (lam0 >= lam1) {
        if (lam0 >= lam2) { o0=0; if (lam1>=lam2){o1=1;o2=2;} else {o1=2;o2=1;} }
        else              { o0=2; o1=0; o2=1; }
      } else {
        if (lam1 >= lam2) { o0=1; if (lam0>=lam2){o1=0;o2=2;} else {o1=2;o2=0;} }
        else              { o0=2; o1=1; o2=0; }
      }
      float v1[3] = {Qm[0][o0], Qm[1][o0], Qm[2][o0]};
      float v2[3] = {Qm[0][o1], Qm[1][o1], Qm[2][o1]};
      float v3[3] = {Qm[0][o2], Qm[1][o2], Qm[2][o2]};

      float u1[3], u2[3], u3[3];
      #pragma unroll
      for (int i=0;i<3;i++) {
        u1[i] = e[3*i+0]*v1[0] + e[3*i+1]*v1[1] + e[3*i+2]*v1[2];
        u2[i] = e[3*i+0]*v2[0] + e[3*i+1]*v2[1] + e[3*i+2]*v2[2];
      }
      float in1 = rsqrtf(fmaxf(u1[0]*u1[0]+u1[1]*u1[1]+u1[2]*u1[2], 1e-30f));
      float in2 = rsqrtf(fmaxf(u2[0]*u2[0]+u2[1]*u2[1]+u2[2]*u2[2], 1e-30f));
      #pragma unroll
      for (int i=0;i<3;i++){ u1[i]*=in1; u2[i]*=in2; }
      u3[0] = u1[1]*u2[2] - u1[2]*u2[1];
      u3[1] = u1[2]*u2[0] - u1[0]*u2[2];
      u3[2] = u1[0]*u2[1] - u1[1]*u2[0];
      float in3 = rsqrtf(fmaxf(u3[0]*u3[0]+u3[1]*u3[1]+u3[2]*u3[2], 1e-30f));
      #pragma unroll
      for (int i=0;i<3;i++) u3[i]*=in3;

      float detU = u1[0]*(u2[1]*u3[2]-u2[2]*u3[1])
                 - u1[1]*(u2[0]*u3[2]-u2[2]*u3[0])
                 + u1[2]*(u2[0]*u3[1]-u2[1]*u3[0]);
      float detV = v1[0]*(v2[1]*v3[2]-v2[2]*v3[1])
                 - v1[1]*(v2[0]*v3[2]-v2[2]*v3[0])
                 + v1[2]*(v2[0]*v3[1]-v2[1]*v3[0]);
      float dd = detU * detV;
      sSgnF = (dd > 0.0f) ? 1.0f : ((dd < 0.0f) ? -1.0f : 0.0f);
      #pragma unroll
      for (int i=0;i<3;i++) {
        sUVf[i]    = u1[i];
        sUVf[3+i]  = u2[i];
        sUVf[6+i]  = u3[i];
        sUVf[9+i]  = v1[i];
        sUVf[12+i] = v2[i];
        sUVf[15+i] = v3[i];
        st3[i] = u3[i];
      }
    }
    __syncwarp();

    // parallel R1 build (R2 derived analytically in phase 3 via H-trick)
    if (lane < 9) {
      int i = lane / 3, j = lane % 3;
      float u1i = sUVf[i], u2i = sUVf[3+i], u3i = sUVf[6+i];
      float v1j = sUVf[9+j], v2j = sUVf[12+j], v3j = sUVf[15+j];
      sR1[lane] = ( u2i*v1j - u1i*v2j + u3i*v3j)*sSgnF;
    }
  }
  __syncthreads();

  // ---- phase 3: cheirality, division-free; candidate-2 via H-trick:
  //   aa2 = aa, at2 = at, ab2 = 2*at*bt - ab   (R2 = (2*t t^T - I) R1, |t|=1)
  float R1[9];
  #pragma unroll
  for (int i=0;i<9;i++) R1[i]=sR1[i];
  const float tv0=st3[0], tv1=st3[1], tv2=st3[2];

  float sc0=0.f, sc1=0.f, sc2=0.f, sc3=0.f;
  if (affine) {
    #pragma unroll
    for (int k = 0; k < NPTS/256; k++) {
      int n = tid + k*256;
      float4 q = sP[n];
      float w = sW[n];
      float bb = q.z*q.z + q.w*q.w + 1.0f;
      float bt = q.z*tv0 + q.w*tv1 + tv2;
      float a0 = R1[0]*q.x + R1[1]*q.y + R1[2];
      float a1 = R1[3]*q.x + R1[4]*q.y + R1[5];
      float a2 = R1[6]*q.x + R1[7]*q.y + R1[8];
      float aa = a0*a0 + a1*a1 + a2*a2;
      float ab = a0*q.z + a1*q.w + a2;
      float at = a0*tv0 + a1*tv1 + a2*tv2;
      {
        float det = aa*bb - ab*ab + 1e-9f;
        float n0 = -at*bb + ab*bt;
        float n1 = aa*bt - ab*at;
        bool dpn = det >= 0.f;
        if (dpn ? (n0 > 0.f && n1 > 0.f) : (n0 < 0.f && n1 < 0.f)) sc0 += w;
        if (dpn ? (n0 < 0.f && n1 < 0.f) : (n0 > 0.f && n1 > 0.f)) sc1 += w;
      }
      {
        float ab2 = 2.0f*at*bt - ab;
        float det = aa*bb - ab2*ab2 + 1e-9f;
        float n0 = -at*bb + ab2*bt;
        float n1 = aa*bt - ab2*at;
        bool dpn = det >= 0.f;
        if (dpn ? (n0 > 0.f && n1 > 0.f) : (n0 < 0.f && n1 < 0.f)) sc2 += w;
        if (dpn ? (n0 < 0.f && n1 < 0.f) : (n0 > 0.f && n1 > 0.f)) sc3 += w;
      }
    }
  } else {
    #pragma unroll
    for (int k = 0; k < NPTS/256; k++) {
      int n = tid + k*256;
      float2 p0 = kp0[n]; float2 p1 = kp1[n]; float w = wv[n];
      float x00 = Ki0[0]*p0.x + Ki0[1]*p0.y + Ki0[2];
      float x01 = Ki0[3]*p0.x + Ki0[4]*p0.y + Ki0[5];
      float x02 = Ki0[6]*p0.x + Ki0[7]*p0.y + Ki0[8];
      float x10 = Ki1[0]*p1.x + Ki1[1]*p1.y + Ki1[2];
      float x11 = Ki1[3]*p1.x + Ki1[4]*p1.y + Ki1[5];
      float x12 = Ki1[6]*p1.x + Ki1[7]*p1.y + Ki1[8];
      float bb = x10*x10 + x11*x11 + x12*x12;
      float bt = x10*tv0 + x11*tv1 + x12*tv2;
      float a0 = R1[0]*x00 + R1[1]*x01 + R1[2]*x02;
      float a1 = R1[3]*x00 + R1[4]*x01 + R1[5]*x02;
      float a2 = R1[6]*x00 + R1[7]*x01 + R1[8]*x02;
      float aa = a0*a0 + a1*a1 + a2*a2;
      float ab = a0*x10 + a1*x11 + a2*x12;
      float at = a0*tv0 + a1*tv1 + a2*tv2;
      {
        float det = aa*bb - ab*ab + 1e-9f;
        float n0 = -at*bb + ab*bt;
        float n1 = aa*bt - ab*at;
        bool dpn = det >= 0.f;
        if (dpn ? (n0 > 0.f && n1 > 0.f) : (n0 < 0.f && n1 < 0.f)) sc0 += w;
        if (dpn ? (n0 < 0.f && n1 < 0.f) : (n0 > 0.f && n1 > 0.f)) sc1 += w;
      }
      {
        float ab2 = 2.0f*at*bt - ab;
        float det = aa*bb - ab2*ab2 + 1e-9f;
        float n0 = -at*bb + ab2*bt;
        float n1 = aa*bt - ab2*at;
        bool dpn = det >= 0.f;
        if (dpn ? (n0 > 0.f && n1 > 0.f) : (n0 < 0.f && n1 < 0.f)) sc2 += w;
        if (dpn ? (n0 < 0.f && n1 < 0.f) : (n0 > 0.f && n1 > 0.f)) sc3 += w;
      }
    }
  }
  #pragma unroll
  for (int off=16; off; off>>=1) {
    sc0 += __shfl_down_sync(FULLM, sc0, off);
    sc1 += __shfl_down_sync(FULLM, sc1, off);
    sc2 += __shfl_down_sync(FULLM, sc2, off);
    sc3 += __shfl_down_sync(FULLM, sc3, off);
  }
  if (lane == 0) { sred[warp][0]=sc0; sred[warp][1]=sc1; sred[warp][2]=sc2; sred[warp][3]=sc3; }
  __syncthreads();
  if (tid == 0) {
    float s0=0.f, s1=0.f, s2=0.f, s3=0.f;
    #pragma unroll
    for (int wp=0; wp<8; wp++){ s0+=sred[wp][0]; s1+=sred[wp][1]; s2+=sred[wp][2]; s3+=sred[wp][3]; }
    float bs = s0; int bi = 0;
    if (s1 > bs){ bs=s1; bi=1; }
    if (s2 > bs){ bs=s2; bi=2; }
    if (s3 > bs){ bs=s3; bi=3; }
    // build selected R: bi<2 -> R1; else R2 = (2 t t^T - I) R1
    float Rsel[9];
    if (bi < 2) {
      #pragma unroll
      for (int i=0;i<9;i++) Rsel[i] = sR1[i];
    } else {
      float t3[3] = {st3[0], st3[1], st3[2]};
      #pragma unroll
      for (int i=0;i<3;i++) {
        #pragma unroll
        for (int j=0;j<3;j++) {
          float dotc = t3[0]*sR1[0*3+j] + t3[1]*sR1[1*3+j] + t3[2]*sR1[2*3+j];
          Rsel[i*3+j] = 2.0f*t3[i]*dotc - sR1[i*3+j];
        }
      }
    }
    float sgn = (bi & 1) ? -1.f : 1.f;
    float ts = tscale[b*2];
    float t0 = (sgn*st3[0])*ts;
    float t1 = (sgn*st3[1])*ts;
    float t2 = (sgn*st3[2])*ts;
    float* o = out + (size_t)b*32;
    o[0]=Rsel[0]; o[1]=Rsel[1]; o[2]=Rsel[2];  o[3]=t0;
    o[4]=Rsel[3]; o[5]=Rsel[4]; o[6]=Rsel[5];  o[7]=t1;
    o[8]=Rsel[6]; o[9]=Rsel[7]; o[10]=Rsel[8]; o[11]=t2;
    o[12]=0.f; o[13]=0.f; o[14]=0.f; o[15]=1.f;
    float ti0 = -(Rsel[0]*t0 + Rsel[3]*t1 + Rsel[6]*t2);
    float ti1 = -(Rsel[1]*t0 + Rsel[4]*t1 + Rsel[7]*t2);
    float ti2 = -(Rsel[2]*t0 + Rsel[5]*t1 + Rsel[8]*t2);
    o[16]=Rsel[0]; o[17]=Rsel[3]; o[18]=Rsel[6]; o[19]=ti0;
    o[20]=Rsel[1]; o[21]=Rsel[4]; o[22]=Rsel[7]; o[23]=ti1;
    o[24]=Rsel[2]; o[25]=Rsel[5]; o[26]=Rsel[8]; o[27]=ti2;
    o[28]=0.f; o[29]=0.f; o[30]=0.f; o[31]=1.f;
  }
}

extern "C" void kernel_launch(void* const* d_in, const int* in_sizes, int n_in,
                              void* d_out, int out_size) {
  const float* kpts0  = (const float*)d_in[0];
  const float* kpts1  = (const float*)d_in[1];
  const float* conf   = (const float*)d_in[2];
  const float* tscale = (const float*)d_in[3];
  const float* Kmat   = (const float*)d_in[4];
  float* out = (float*)d_out;

  cudaFuncSetAttribute(k_fused, cudaFuncAttributeMaxDynamicSharedMemorySize, DYN_SMEM);
  k_fused<<<BATCH, 256, DYN_SMEM>>>(kpts0, kpts1, conf, tscale, Kmat, out);
}

// round 14
// speedup vs baseline: 1.8602x; 1.0406x over previous
#include <cuda_runtime.h>

#define BATCH 256
#define NPTS  4096
#define DYN_SMEM (2*(NPTS*16 + NPTS*4))
#define FULLM 0xffffffffu

// ---------- fast double helpers: fp32 seed + 1 Newton step ----------
__device__ __forceinline__ double drecip(double x) {
  double y = (double)__fdividef(1.0f, (float)x);
  y = y * (2.0 - x * y);
  return y;
}
__device__ __forceinline__ double drsqrt(double x) {
  double y = (double)rsqrtf((float)x);
  y = y * (1.5 - 0.5 * x * y * y);
  return y;
}

__device__ __forceinline__ void inv3x3(const float* __restrict__ Km, float* __restrict__ out) {
  double a=Km[0], b=Km[1], c=Km[2], d=Km[3], e=Km[4], f=Km[5], g=Km[6], h=Km[7], i=Km[8];
  double det = a*(e*i - f*h) - b*(d*i - f*g) + c*(d*h - e*g);
  double inv = 1.0 / det;
  out[0]=(float)((e*i - f*h)*inv); out[1]=(float)((c*h - b*i)*inv); out[2]=(float)((b*f - c*e)*inv);
  out[3]=(float)((f*g - d*i)*inv); out[4]=(float)((a*i - c*g)*inv); out[5]=(float)((c*d - a*f)*inv);
  out[6]=(float)((d*h - e*g)*inv); out[7]=(float)((b*g - a*h)*inv); out[8]=(float)((a*e - b*d)*inv);
}

__device__ __forceinline__ int p2i(int a, int b) {
  int mn = a < b ? a : b, mx = a < b ? b : a;
  return mn*(5-mn)/2 + mx;
}

template<int P, int Q>
__device__ __forceinline__ void rot3f(float g[3][3], float Qm[3][3]) {
  constexpr int K2 = 3 - P - Q;
  float apq = g[P][Q];
  float app = g[P][P], aqq = g[Q][Q];
  if (fabsf(apq) <= 1e-12f * (fabsf(app) + fabsf(aqq))) return;
  float tau = __fdividef(aqq - app, 2.0f * apq);
  float tt = ((tau >= 0.0f) ? 1.0f : -1.0f) / (fabsf(tau) + sqrtf(1.0f + tau*tau));
  float c = rsqrtf(1.0f + tt*tt);
  float s = tt * c;
  float akp = g[K2][P], akq = g[K2][Q];
  float np = c*akp - s*akq, nq = s*akp + c*akq;
  g[K2][P] = np; g[P][K2] = np;
  g[K2][Q] = nq; g[Q][K2] = nq;
  g[P][P] = app - tt*apq;
  g[Q][Q] = aqq + tt*apq;
  g[P][Q] = 0.0f; g[Q][P] = 0.0f;
  #pragma unroll
  for (int r = 0; r < 3; r++) {
    float qp = Qm[r][P], qq = Qm[r][Q];
    Qm[r][P] = c*qp - s*qq;
    Qm[r][Q] = s*qp + c*qq;
  }
}

// ---------- single fused kernel: one block per TWO batches ----------
__global__ __launch_bounds__(256, 1) void k_fused(const float* __restrict__ kpts0,
                                                  const float* __restrict__ kpts1,
                                                  const float* __restrict__ conf,
                                                  const float* __restrict__ tscale,
                                                  const float* __restrict__ Kmat,
                                                  float* __restrict__ out) {
  const int tid = threadIdx.x;
  const int warp = tid >> 5, lane = tid & 31;

  extern __shared__ char dyn[];
  // layout: sP(batch0)[64KB] | sP(batch1)[64KB] | sW(batch0)[16KB] | sW(batch1)[16KB]
  float4* sPv0 = (float4*)dyn;
  float4* sPv1 = (float4*)(dyn + NPTS*16);
  float*  sWv0 = (float*)(dyn + 2*NPTS*16);
  float*  sWv1 = (float*)(dyn + 2*NPTS*16 + NPTS*4);

  __shared__ float sKi[2][18];
  __shared__ float sred[8][36];
  __shared__ double sd[2][81];
  __shared__ float sT[2][36];
  __shared__ float sR1[2][9], st3[2][3];
  __shared__ float scs[2][4], sss[2][4];
  __shared__ double sDinv[2][9], sSigma[2], sxd[2][9];
  __shared__ float sUVf[2][18], sSgnF[2];
  __shared__ int sIpiv[2][9];
  __shared__ int sPerm[2][9];
  __shared__ int sAffine[2];

  // ---- phase 0: K inverses for both batches ----
  if (tid < 2) {
    int bb = blockIdx.x*2 + tid;
    float ki0[9], ki1[9];
    inv3x3(Kmat + bb*18, ki0);
    inv3x3(Kmat + bb*18 + 9, ki1);
    #pragma unroll
    for (int i=0;i<9;i++) { sKi[tid][i]=ki0[i]; sKi[tid][9+i]=ki1[i]; }
    sAffine[tid] = (ki0[6]==0.f && ki0[7]==0.f && ki0[8]==1.f &&
                    ki1[6]==0.f && ki1[7]==0.f && ki1[8]==1.f) ? 1 : 0;
  }
  __syncthreads();

  // ---- phase 1: accumulate T[6][6] + stage coords, for s = 0,1 ----
  for (int s = 0; s < 2; s++) {
    const int bb = blockIdx.x*2 + s;
    float Ki0[9], Ki1[9];
    #pragma unroll
    for (int i=0;i<9;i++){ Ki0[i]=sKi[s][i]; Ki1[i]=sKi[s][9+i]; }
    const float2* kp0 = (const float2*)(kpts0) + (size_t)bb*NPTS;
    const float2* kp1 = (const float2*)(kpts1) + (size_t)bb*NPTS;
    const float*  wv  = conf + (size_t)bb*NPTS;
    float4* sP = s ? sPv1 : sPv0;
    float*  sW = s ? sWv1 : sWv0;

    float acc[36];
    #pragma unroll
    for (int i=0;i<36;i++) acc[i]=0.f;

    float2 b0[4], b1[4]; float bwv[4];
    #pragma unroll
    for (int i=0;i<4;i++) {
      b0[i] = kp0[tid + i*256];
      b1[i] = kp1[tid + i*256];
      bwv[i] = wv[tid + i*256];
    }
    #pragma unroll
    for (int k = 0; k < NPTS/256; k++) {
      float2 c0 = b0[k & 3], c1 = b1[k & 3];
      float  cw = bwv[k & 3];
      if (k + 4 < NPTS/256) {
        b0[k & 3] = kp0[tid + (k+4)*256];
        b1[k & 3] = kp1[tid + (k+4)*256];
        bwv[k & 3] = wv[tid + (k+4)*256];
      }
      float x00 = Ki0[0]*c0.x + Ki0[1]*c0.y + Ki0[2];
      float x01 = Ki0[3]*c0.x + Ki0[4]*c0.y + Ki0[5];
      float x02 = Ki0[6]*c0.x + Ki0[7]*c0.y + Ki0[8];
      float x10 = Ki1[0]*c1.x + Ki1[1]*c1.y + Ki1[2];
      float x11 = Ki1[3]*c1.x + Ki1[4]*c1.y + Ki1[5];
      float x12 = Ki1[6]*c1.x + Ki1[7]*c1.y + Ki1[8];
      int n = tid + k*256;
      sP[n] = make_float4(x00, x01, x10, x11);
      sW[n] = cw;
      float s0a[6] = {x00*x00, x00*x01, x00*x02, x01*x01, x01*x02, x02*x02};
      float s1a[6] = {x10*x10, x10*x11, x10*x12, x11*x11, x11*x12, x12*x12};
      float ws1[6];
      #pragma unroll
      for (int a=0;a<6;a++) ws1[a] = cw*s1a[a];
      #pragma unroll
      for (int a=0;a<6;a++)
        #pragma unroll
        for (int bb2=0;bb2<6;bb2++)
          acc[a*6+bb2] = fmaf(ws1[a], s0a[bb2], acc[a*6+bb2]);
    }
    #pragma unroll
    for (int i=0;i<36;i++) {
      acc[i] += __shfl_down_sync(FULLM, acc[i], 16);
      acc[i] += __shfl_down_sync(FULLM, acc[i], 8);
      acc[i] += __shfl_down_sync(FULLM, acc[i], 4);
      acc[i] += __shfl_down_sync(FULLM, acc[i], 2);
      acc[i] += __shfl_down_sync(FULLM, acc[i], 1);
    }
    if (lane == 0) {
      #pragma unroll
      for (int i=0;i<36;i++) sred[warp][i] = acc[i];
    }
    __syncthreads();
    if (tid < 36) {
      float v = 0.f;
      #pragma unroll
      for (int wp=0; wp<8; wp++) v += sred[wp][tid];
      sT[s][tid] = v;
    }
    __syncthreads();
  }

  // ---- phase 2: TWO concurrent eigensolves (warp 0 -> batch 0, warp 1 -> batch 1) ----
  if (warp < 2) {
    const int s = warp;
    float* A = (float*)&sd[s][0];   // 81 floats

    if (lane < 9) {
      const int i0 = lane / 3, j0 = lane % 3;
      #pragma unroll
      for (int j = 0; j < 9; j++)
        A[lane*9+j] = sT[s][p2i(i0, j/3)*6 + p2i(j0, j%3)];
    }
    __syncwarp();

    // Phase A: parallel-ordered fp32 Jacobi, 3 sweeps, sigma only
    for (int sweep = 0; sweep < 3; sweep++) {
      for (int r = 0; r < 9; r++) {
        const int bye = (5 * ((2*r) % 9)) % 9;
        if (lane < 4) {
          int d = lane + 1;
          int a = (bye + d) % 9;
          int bq = (bye + 9 - d) % 9;
          int p = a < bq ? a : bq;
          int q = a < bq ? bq : a;
          float apq = A[p*9+q], app = A[p*9+p], aqq = A[q*9+q];
          float c = 1.0f, sv = 0.0f;
          if (fabsf(apq) > 6e-8f * (fabsf(app) + fabsf(aqq))) {
            float tau = __fdividef(aqq - app, 2.0f * apq);
            float t = ((tau >= 0.0f) ? 1.0f : -1.0f) / (fabsf(tau) + sqrtf(1.0f + tau*tau));
            c = rsqrtf(1.0f + t*t);
            sv = t * c;
          }
          scs[s][lane] = c; sss[s][lane] = sv;
        }
        __syncwarp();
        float cr[4], sr[4];
        int pr[4], qr[4];
        #pragma unroll
        for (int d = 0; d < 4; d++) {
          cr[d] = scs[s][d]; sr[d] = sss[s][d];
          int a = (bye + d + 1) % 9;
          int bq = (bye + 8 - d) % 9;
          pr[d] = a < bq ? a : bq;
          qr[d] = a < bq ? bq : a;
        }
        if (lane < 9) {
          #pragma unroll
          for (int d = 0; d < 4; d++) {
            int p = pr[d], q = qr[d];
            float vp = A[lane*9+p], vq = A[lane*9+q];
            A[lane*9+p] = cr[d]*vp - sr[d]*vq;
            A[lane*9+q] = sr[d]*vp + cr[d]*vq;
          }
        }
        __syncwarp();
        if (lane < 9) {
          #pragma unroll
          for (int d = 0; d < 4; d++) {
            int p = pr[d], q = qr[d];
            float vp = A[p*9+lane], vq = A[q*9+lane];
            A[p*9+lane] = cr[d]*vp - sr[d]*vq;
            A[q*9+lane] = sr[d]*vp + cr[d]*vq;
          }
        }
        __syncwarp();
      }
    }

    if (lane == 0) {
      float mv = A[0];
      #pragma unroll
      for (int k=1;k<9;k++) mv = fminf(mv, A[k*9+k]);
      sSigma[s] = (double)mv;
    }
    __syncwarp();
    double sigma = sSigma[s];

    // build D = M - sigma*I in parallel (overwrite A region)
    double* D = &sd[s][0];
    if (lane < 9) {
      int i0 = lane/3, j0 = lane%3;
      #pragma unroll
      for (int j=0;j<9;j++)
        D[lane*9+j] = (double)sT[s][p2i(i0, j/3)*6 + p2i(j0, j%3)];
      D[lane*9+lane] -= sigma;
    }
    __syncwarp();

    // parallel LU with partial pivoting; shuffle pivot search
    for (int k=0;k<9;k++) {
      double av = (lane < 9 && lane >= k) ? fabs(D[lane*9+k]) : -1.0;
      int ai = lane;
      #pragma unroll
      for (int off=16; off; off>>=1) {
        double ov = __shfl_xor_sync(FULLM, av, off);
        int oi = __shfl_xor_sync(FULLM, ai, off);
        if (ov > av || (ov == av && oi < ai)) { av = ov; ai = oi; }
      }
      int p = ai;
      if (lane == 0) sIpiv[s][k] = p;
      if (p != k && lane < 9) {
        double t = D[k*9+lane]; D[k*9+lane] = D[p*9+lane]; D[p*9+lane] = t;
      }
      __syncwarp();
      double pv = D[k*9+k];
      if (fabs(pv) < 1e-30) pv = (pv >= 0.0) ? 1e-30 : -1e-30;
      double ipv = drecip(pv);
      if (lane == 0) sDinv[s][k] = ipv;
      if (lane > k && lane < 9) {
        double l = D[lane*9+k] * ipv;
        D[lane*9+k] = l;
        for (int j=k+1;j<9;j++) D[lane*9+j] -= l * D[k*9+j];
      }
      __syncwarp();
    }

    // permutation map
    if (lane == 0) {
      int idx[9];
      #pragma unroll
      for (int i=0;i<9;i++) idx[i]=i;
      for (int k=0;k<9;k++){ int p=sIpiv[s][k]; int t=idx[k]; idx[k]=idx[p]; idx[p]=t; }
      #pragma unroll
      for (int i=0;i<9;i++) sPerm[s][i]=idx[i];
    }
    __syncwarp();

    double row[9]; double dinv_l = 1.0; int permL = 0;
    if (lane < 9) {
      #pragma unroll
      for (int j=0;j<9;j++) row[j] = D[lane*9+j];
      dinv_l = sDinv[s][lane];
      permL = sPerm[s][lane];
    }

    // lane-parallel inverse iteration: 2 solves from ones vector
    double rv = 1.0;
    for (int it=0; it<2; it++) {
      if (lane < 9) sxd[s][lane] = rv;
      __syncwarp();
      if (lane < 9) rv = sxd[s][permL];
      __syncwarp();
      #pragma unroll
      for (int j=0;j<8;j++) {
        double yj = __shfl_sync(FULLM, rv, j);
        if (lane > j && lane < 9) rv -= row[j]*yj;
      }
      #pragma unroll
      for (int j=8;j>=0;j--) {
        if (lane == j) rv *= dinv_l;
        double xj = __shfl_sync(FULLM, rv, j);
        if (lane < j) rv -= row[j]*xj;
      }
      double c2 = (lane < 9) ? rv*rv : 0.0;
      #pragma unroll
      for (int off=16; off; off>>=1) c2 += __shfl_xor_sync(FULLM, c2, off);
      rv *= drsqrt(c2);
    }
    if (lane < 9) sxd[s][lane] = rv;
    __syncwarp();

    // lane 0: 3x3 SVD of E in fp32
    if (lane == 0) {
      float e[9];
      #pragma unroll
      for (int k=0;k<9;k++) e[k] = (float)sxd[s][k];

      float G3[3][3];
      #pragma unroll
      for (int i=0;i<3;i++)
        #pragma unroll
        for (int j=0;j<3;j++)
          G3[i][j] = e[0+i]*e[0+j] + e[3+i]*e[3+j] + e[6+i]*e[6+j];

      float Qm[3][3] = {{1.f,0.f,0.f},{0.f,1.f,0.f},{0.f,0.f,1.f}};
      #pragma unroll
      for (int sw=0; sw<4; sw++) { rot3f<0,1>(G3,Qm); rot3f<0,2>(G3,Qm); rot3f<1,2>(G3,Qm); }

      float lam0=G3[0][0], lam1=G3[1][1], lam2=G3[2][2];
      int o0, o1, o2;
      if (lam0 >= lam1) {
        if (lam0 >= lam2) { o0=0; if (lam1>=lam2){o1=1;o2=2;} else {o1=2;o2=1;} }
        else              { o0=2; o1=0; o2=1; }
      } else {
        if (lam1 >= lam2) { o0=1; if (lam0>=lam2){o1=0;o2=2;} else {o1=2;o2=0;} }
        else              { o0=2; o1=1; o2=0; }
      }
      float v1[3] = {Qm[0][o0], Qm[1][o0], Qm[2][o0]};
      float v2[3] = {Qm[0][o1], Qm[1][o1], Qm[2][o1]};
      float v3[3] = {Qm[0][o2], Qm[1][o2], Qm[2][o2]};

      float u1[3], u2[3], u3[3];
      #pragma unroll
      for (int i=0;i<3;i++) {
        u1[i] = e[3*i+0]*v1[0] + e[3*i+1]*v1[1] + e[3*i+2]*v1[2];
        u2[i] = e[3*i+0]*v2[0] + e[3*i+1]*v2[1] + e[3*i+2]*v2[2];
      }
      float in1 = rsqrtf(fmaxf(u1[0]*u1[0]+u1[1]*u1[1]+u1[2]*u1[2], 1e-30f));
      float in2 = rsqrtf(fmaxf(u2[0]*u2[0]+u2[1]*u2[1]+u2[2]*u2[2], 1e-30f));
      #pragma unroll
      for (int i=0;i<3;i++){ u1[i]*=in1; u2[i]*=in2; }
      u3[0] = u1[1]*u2[2] - u1[2]*u2[1];
      u3[1] = u1[2]*u2[0] - u1[0]*u2[2];
      u3[2] = u1[0]*u2[1] - u1[1]*u2[0];
      float in3 = rsqrtf(fmaxf(u3[0]*u3[0]+u3[1]*u3[1]+u3[2]*u3[2], 1e-30f));
      #pragma unroll
      for (int i=0;i<3;i++) u3[i]*=in3;

      float detU = u1[0]*(u2[1]*u3[2]-u2[2]*u3[1])
                 - u1[1]*(u2[0]*u3[2]-u2[2]*u3[0])
                 + u1[2]*(u2[0]*u3[1]-u2[1]*u3[0]);
      float detV = v1[0]*(v2[1]*v3[2]-v2[2]*v3[1])
                 - v1[1]*(v2[0]*v3[2]-v2[2]*v3[0])
                 + v1[2]*(v2[0]*v3[1]-v2[1]*v3[0]);
      float dd = detU * detV;
      sSgnF[s] = (dd > 0.0f) ? 1.0f : ((dd < 0.0f) ? -1.0f : 0.0f);
      #pragma unroll
      for (int i=0;i<3;i++) {
        sUVf[s][i]    = u1[i];
        sUVf[s][3+i]  = u2[i];
        sUVf[s][6+i]  = u3[i];
        sUVf[s][9+i]  = v1[i];
        sUVf[s][12+i] = v2[i];
        sUVf[s][15+i] = v3[i];
        st3[s][i] = u3[i];
      }
    }
    __syncwarp();

    // parallel R1 build (R2 derived via H-trick downstream)
    if (lane < 9) {
      int i = lane / 3, j = lane % 3;
      float u1i = sUVf[s][i], u2i = sUVf[s][3+i], u3i = sUVf[s][6+i];
      float v1j = sUVf[s][9+j], v2j = sUVf[s][12+j], v3j = sUVf[s][15+j];
      sR1[s][lane] = ( u2i*v1j - u1i*v2j + u3i*v3j)*sSgnF[s];
    }
  }
  __syncthreads();

  // ---- phase 3: cheirality per batch (division-free; H-trick for candidate 2) ----
  for (int s = 0; s < 2; s++) {
    const int bb = blockIdx.x*2 + s;
    float R1[9];
    #pragma unroll
    for (int i=0;i<9;i++) R1[i]=sR1[s][i];
    const float tv0=st3[s][0], tv1=st3[s][1], tv2=st3[s][2];
    float4* sP = s ? sPv1 : sPv0;
    float*  sW = s ? sWv1 : sWv0;

    float sc0=0.f, sc1=0.f, sc2=0.f, sc3=0.f;
    if (sAffine[s]) {
      #pragma unroll
      for (int k = 0; k < NPTS/256; k++) {
        int n = tid + k*256;
        float4 q = sP[n];
        float w = sW[n];
        float bb2v = q.z*q.z + q.w*q.w + 1.0f;
        float bt = q.z*tv0 + q.w*tv1 + tv2;
        float a0 = R1[0]*q.x + R1[1]*q.y + R1[2];
        float a1 = R1[3]*q.x + R1[4]*q.y + R1[5];
        float a2 = R1[6]*q.x + R1[7]*q.y + R1[8];
        float aa = a0*a0 + a1*a1 + a2*a2;
        float ab = a0*q.z + a1*q.w + a2;
        float at = a0*tv0 + a1*tv1 + a2*tv2;
        {
          float det = aa*bb2v - ab*ab + 1e-9f;
          float n0 = -at*bb2v + ab*bt;
          float n1 = aa*bt - ab*at;
          bool dpn = det >= 0.f;
          if (dpn ? (n0 > 0.f && n1 > 0.f) : (n0 < 0.f && n1 < 0.f)) sc0 += w;
          if (dpn ? (n0 < 0.f && n1 < 0.f) : (n0 > 0.f && n1 > 0.f)) sc1 += w;
        }
        {
          float ab2 = 2.0f*at*bt - ab;
          float det = aa*bb2v - ab2*ab2 + 1e-9f;
          float n0 = -at*bb2v + ab2*bt;
          float n1 = aa*bt - ab2*at;
          bool dpn = det >= 0.f;
          if (dpn ? (n0 > 0.f && n1 > 0.f) : (n0 < 0.f && n1 < 0.f)) sc2 += w;
          if (dpn ? (n0 < 0.f && n1 < 0.f) : (n0 > 0.f && n1 > 0.f)) sc3 += w;
        }
      }
    } else {
      const float2* kp0 = (const float2*)(kpts0) + (size_t)bb*NPTS;
      const float2* kp1 = (const float2*)(kpts1) + (size_t)bb*NPTS;
      const float*  wv  = conf + (size_t)bb*NPTS;
      float Ki0[9], Ki1[9];
      #pragma unroll
      for (int i=0;i<9;i++){ Ki0[i]=sKi[s][i]; Ki1[i]=sKi[s][9+i]; }
      #pragma unroll
      for (int k = 0; k < NPTS/256; k++) {
        int n = tid + k*256;
        float2 p0 = kp0[n]; float2 p1 = kp1[n]; float w = wv[n];
        float x00 = Ki0[0]*p0.x + Ki0[1]*p0.y + Ki0[2];
        float x01 = Ki0[3]*p0.x + Ki0[4]*p0.y + Ki0[5];
        float x02 = Ki0[6]*p0.x + Ki0[7]*p0.y + Ki0[8];
        float x10 = Ki1[0]*p1.x + Ki1[1]*p1.y + Ki1[2];
        float x11 = Ki1[3]*p1.x + Ki1[4]*p1.y + Ki1[5];
        float x12 = Ki1[6]*p1.x + Ki1[7]*p1.y + Ki1[8];
        float bb2v = x10*x10 + x11*x11 + x12*x12;
        float bt = x10*tv0 + x11*tv1 + x12*tv2;
        float a0 = R1[0]*x00 + R1[1]*x01 + R1[2]*x02;
        float a1 = R1[3]*x00 + R1[4]*x01 + R1[5]*x02;
        float a2 = R1[6]*x00 + R1[7]*x01 + R1[8]*x02;
        float aa = a0*a0 + a1*a1 + a2*a2;
        float ab = a0*x10 + a1*x11 + a2*x12;
        float at = a0*tv0 + a1*tv1 + a2*tv2;
        {
          float det = aa*bb2v - ab*ab + 1e-9f;
          float n0 = -at*bb2v + ab*bt;
          float n1 = aa*bt - ab*at;
          bool dpn = det >= 0.f;
          if (dpn ? (n0 > 0.f && n1 > 0.f) : (n0 < 0.f && n1 < 0.f)) sc0 += w;
          if (dpn ? (n0 < 0.f && n1 < 0.f) : (n0 > 0.f && n1 > 0.f)) sc1 += w;
        }
        {
          float ab2 = 2.0f*at*bt - ab;
          float det = aa*bb2v - ab2*ab2 + 1e-9f;
          float n0 = -at*bb2v + ab2*bt;
          float n1 = aa*bt - ab2*at;
          bool dpn = det >= 0.f;
          if (dpn ? (n0 > 0.f && n1 > 0.f) : (n0 < 0.f && n1 < 0.f)) sc2 += w;
          if (dpn ? (n0 < 0.f && n1 < 0.f) : (n0 > 0.f && n1 > 0.f)) sc3 += w;
        }
      }
    }
    #pragma unroll
    for (int off=16; off; off>>=1) {
      sc0 += __shfl_down_sync(FULLM, sc0, off);
      sc1 += __shfl_down_sync(FULLM, sc1, off);
      sc2 += __shfl_down_sync(FULLM, sc2, off);
      sc3 += __shfl_down_sync(FULLM, sc3, off);
    }
    if (lane == 0) { sred[warp][0]=sc0; sred[warp][1]=sc1; sred[warp][2]=sc2; sred[warp][3]=sc3; }
    __syncthreads();
    if (tid == 0) {
      float s0=0.f, s1=0.f, s2=0.f, s3=0.f;
      #pragma unroll
      for (int wp=0; wp<8; wp++){ s0+=sred[wp][0]; s1+=sred[wp][1]; s2+=sred[wp][2]; s3+=sred[wp][3]; }
      float bs = s0; int bi = 0;
      if (s1 > bs){ bs=s1; bi=1; }
      if (s2 > bs){ bs=s2; bi=2; }
      if (s3 > bs){ bs=s3; bi=3; }
      float Rsel[9];
      if (bi < 2) {
        #pragma unroll
        for (int i=0;i<9;i++) Rsel[i] = sR1[s][i];
      } else {
        float t3a[3] = {st3[s][0], st3[s][1], st3[s][2]};
        #pragma unroll
        for (int i=0;i<3;i++) {
          #pragma unroll
          for (int j=0;j<3;j++) {
            float dotc = t3a[0]*sR1[s][0*3+j] + t3a[1]*sR1[s][1*3+j] + t3a[2]*sR1[s][2*3+j];
            Rsel[i*3+j] = 2.0f*t3a[i]*dotc - sR1[s][i*3+j];
          }
        }
      }
      float sgn = (bi & 1) ? -1.f : 1.f;
      float ts = tscale[bb*2];
      float t0 = (sgn*st3[s][0])*ts;
      float t1 = (sgn*st3[s][1])*ts;
      float t2 = (sgn*st3[s][2])*ts;
      float* o = out + (size_t)bb*32;
      o[0]=Rsel[0]; o[1]=Rsel[1]; o[2]=Rsel[2];  o[3]=t0;
      o[4]=Rsel[3]; o[5]=Rsel[4]; o[6]=Rsel[5];  o[7]=t1;
      o[8]=Rsel[6]; o[9]=Rsel[7]; o[10]=Rsel[8]; o[11]=t2;
      o[12]=0.f; o[13]=0.f; o[14]=0.f; o[15]=1.f;
      float ti0 = -(Rsel[0]*t0 + Rsel[3]*t1 + Rsel[6]*t2);
      float ti1 = -(Rsel[1]*t0 + Rsel[4]*t1 + Rsel[7]*t2);
      float ti2 = -(Rsel[2]*t0 + Rsel[5]*t1 + Rsel[8]*t2);
      o[16]=Rsel[0]; o[17]=Rsel[3]; o[18]=Rsel[6]; o[19]=ti0;
      o[20]=Rsel[1]; o[21]=Rsel[4]; o[22]=Rsel[7]; o[23]=ti1;
      o[24]=Rsel[2]; o[25]=Rsel[5]; o[26]=Rsel[8]; o[27]=ti2;
      o[28]=0.f; o[29]=0.f; o[30]=0.f; o[31]=1.f;
    }
    __syncthreads();
  }
}

extern "C" void kernel_launch(void* const* d_in, const int* in_sizes, int n_in,
                              void* d_out, int out_size) {
  const float* kpts0  = (const float*)d_in[0];
  const float* kpts1  = (const float*)d_in[1];
  const float* conf   = (const float*)d_in[2];
  const float* tscale = (const float*)d_in[3];
  const float* Kmat   = (const float*)d_in[4];
  float* out = (float*)d_out;

  cudaFuncSetAttribute(k_fused, cudaFuncAttributeMaxDynamicSharedMemorySize, DYN_SMEM);
  k_fused<<<BATCH/2, 256, DYN_SMEM>>>(kpts0, kpts1, conf, tscale, Kmat, out);
}